// round 13
// baseline (speedup 1.0000x reference)
#include <cuda_runtime.h>
#include <cuda_bf16.h>
#include <math.h>
#include <stdint.h>

#define N0V 4096
#define N1V 16384
#define HIDV 128
#define LATV 64
#define NOFF 21

__constant__ int c_aug[NOFF] = {1,2,3,4,5,6,7,8,9,10,11,12,13,14,15,16,17,18,19,21,24};

// scratch (static device globals; allocation-free)
__device__ float g_xa[N1V * HIDV];
__device__ float g_xb[N1V * HIDV];
__device__ float g_u [N1V * HIDV];
__device__ float g_v [N1V * HIDV];
__device__ float g_l [N1V * HIDV];
__device__ int   g_idx[N1V * 3];
__device__ float g_w  [N1V * 3];
// pre-swizzled weight images: per mat 128 rows x 256B = 2048 uint4
__device__ uint4  g_wswh[12 * 2048];
__device__ uint4  g_wswl[12 * 2048];
__device__ float4 g_Q[12 * HIDV];
__device__ float4 g_E[12 * HIDV];

__device__ __forceinline__ float warp_sum(float x) {
    #pragma unroll
    for (int o = 16; o; o >>= 1) x += __shfl_xor_sync(0xffffffffu, x, o);
    return x;
}
__device__ __forceinline__ float warp_max(float x) {
    #pragma unroll
    for (int o = 16; o; o >>= 1) x = fmaxf(x, __shfl_xor_sync(0xffffffffu, x, o));
    return x;
}

__device__ __forceinline__ uint32_t smem_u32(const void* p) {
    uint32_t a;
    asm("{ .reg .u64 t; cvta.to.shared.u64 t, %1; cvt.u32.u64 %0, t; }"
        : "=r"(a) : "l"(p));
    return a;
}

#define LDSM_X4(r0, r1, r2, r3, addr) \
    asm volatile("ldmatrix.sync.aligned.m8n8.x4.shared.b16 {%0,%1,%2,%3}, [%4];" \
                 : "=r"(r0), "=r"(r1), "=r"(r2), "=r"(r3) : "r"(addr))

#define MMA16816(d, a0, a1, a2, a3, b0, b1) \
    asm volatile("mma.sync.aligned.m16n8k16.row.col.f32.bf16.bf16.f32 " \
                 "{%0,%1,%2,%3}, {%4,%5,%6,%7}, {%8,%9}, {%0,%1,%2,%3};" \
                 : "+f"((d)[0]), "+f"((d)[1]), "+f"((d)[2]), "+f"((d)[3]) \
                 : "r"(a0), "r"(a1), "r"(a2), "r"(a3), "r"(b0), "r"(b1))

__device__ __forceinline__ void cvt_pair(float a, float b, uint32_t& hi, uint32_t& lo) {
    __nv_bfloat16 ha = __float2bfloat16(a), hb = __float2bfloat16(b);
    float ra = a - __bfloat162float(ha);
    float rb = b - __bfloat162float(hb);
    __nv_bfloat162 h2 = __halves2bfloat162(ha, hb);
    __nv_bfloat162 l2 = __halves2bfloat162(__float2bfloat16(ra), __float2bfloat16(rb));
    hi = *reinterpret_cast<uint32_t*>(&h2);
    lo = *reinterpret_cast<uint32_t*>(&l2);
}

// ===========================================================================
// prep: weights -> bf16 hi/lo in FINAL swizzled smem image + Q/E tables.
// image row c (=out col), uint4 index c*16 + (g ^ (c&15)), g = 16B group 0..15
// holding k elements [g*8, g*8+8).
// ===========================================================================
__global__ void prep_weights_kernel(
    const float* __restrict__ Wl, const float* __restrict__ Wr,
    const float* __restrict__ Lw,
    const float* __restrict__ bl, const float* __restrict__ br,
    const float* __restrict__ lb, const float* __restrict__ We)
{
    int mat = blockIdx.x;               // 0..11
    int L = mat / 3, which = mat % 3;
    const float* W    = (which == 0) ? Wl + L * HIDV * 131
                      : (which == 1) ? Wr + L * HIDV * 131
                                     : Lw + L * HIDV * 131;
    const float* bias = (which == 0) ? bl + L * HIDV
                      : (which == 1) ? br + L * HIDV
                                     : lb + L * HIDV;
    int tid = threadIdx.x;
    int c = tid >> 1, h = tid & 1;
    uint4* oh = g_wswh + mat * 2048 + c * 16;
    uint4* ol = g_wswl + mat * 2048 + c * 16;
    int cs = c & 15;
    #pragma unroll
    for (int gg = 0; gg < 8; gg++) {
        int g = h * 8 + gg;
        const float* wr = W + c * 131 + g * 8;
        uint32_t h0, l0, h1, l1, h2, l2, h3, l3;
        cvt_pair(wr[0], wr[1], h0, l0); cvt_pair(wr[2], wr[3], h1, l1);
        cvt_pair(wr[4], wr[5], h2, l2); cvt_pair(wr[6], wr[7], h3, l3);
        int di = g ^ cs;
        oh[di] = make_uint4(h0, h1, h2, h3);
        ol[di] = make_uint4(l0, l1, l2, l3);
    }
    if (tid < HIDV) {
        int cc = tid;
        g_Q[mat * HIDV + cc] = make_float4(W[cc * 131 + 128], W[cc * 131 + 129],
                                           W[cc * 131 + 130], bias[cc]);
        const float* WeL = We + L * HIDV * 3;
        g_E[mat * HIDV + cc] = (which < 2)
            ? make_float4(WeL[cc * 3], WeL[cc * 3 + 1], WeL[cc * 3 + 2], 0.f)
            : make_float4(0.f, 0.f, 0.f, 0.f);
    }
}

// ===========================================================================
// HMMA layer GEMM (R12 structure: 512 threads, 128x128 tile, grid (N/128, 3);
// mat-0 writes only u). B preamble = pure uint4 copy of pre-swizzled image.
// ===========================================================================
#define OFF_AH 0
#define OFF_AL 32768
#define OFF_BH 65536
#define OFF_BL 98304
#define OFF_Q  131072
#define OFF_E  133120
#define GSMEM_TOTAL 135168

__global__ void __launch_bounds__(512, 1) gemm_mma_kernel(
    const float* __restrict__ x, const float* __restrict__ pos,
    const uint4* __restrict__ wsH, const uint4* __restrict__ wsL,
    const float4* __restrict__ Qg, const float4* __restrict__ Eg,
    float* __restrict__ u, float* __restrict__ v, float* __restrict__ l)
{
    extern __shared__ char smem[];
    uint32_t sb = smem_u32(smem);
    int tid = threadIdx.x;
    int w = tid >> 5, t = tid & 31;
    int mat = blockIdx.y;
    int rowbase = blockIdx.x * 128;

    // --- convert X tile -> A_hi/A_lo (in-kernel, R12 verbatim) ---
    {
        int r = tid >> 2, q = tid & 3;
        const float4* xr = (const float4*)(x + (size_t)(rowbase + r) * HIDV + q * 32);
        char* bH = smem + OFF_AH + r * 256;
        char* bL = smem + OFF_AL + r * 256;
        uint32_t xop = (uint32_t)(r & 15) << 4;
        #pragma unroll
        for (int j = 0; j < 4; j++) {
            float4 v0 = xr[j * 2], v1 = xr[j * 2 + 1];
            uint32_t h0, l0, h1, l1, h2, l2, h3, l3;
            cvt_pair(v0.x, v0.y, h0, l0); cvt_pair(v0.z, v0.w, h1, l1);
            cvt_pair(v1.x, v1.y, h2, l2); cvt_pair(v1.z, v1.w, h3, l3);
            uint32_t off = ((uint32_t)(q * 64 + j * 16)) ^ xop;
            *reinterpret_cast<uint4*>(bH + off) = make_uint4(h0, h1, h2, h3);
            *reinterpret_cast<uint4*>(bL + off) = make_uint4(l0, l1, l2, l3);
        }
    }
    // --- B copy: straight uint4 copy of the pre-swizzled image ---
    {
        const uint4* srcH = wsH + (size_t)mat * 2048;
        const uint4* srcL = wsL + (size_t)mat * 2048;
        uint4* dH = reinterpret_cast<uint4*>(smem + OFF_BH);
        uint4* dL = reinterpret_cast<uint4*>(smem + OFF_BL);
        #pragma unroll
        for (int j = 0; j < 4; j++) {
            int i = tid + j * 512;
            dH[i] = srcH[i];
            dL[i] = srcL[i];
        }
    }
    // --- Q/E copy ---
    if (tid < 128) {
        *reinterpret_cast<float4*>(smem + OFF_Q + tid * 16) = Qg[mat * HIDV + tid];
    } else if (tid < 256) {
        *reinterpret_cast<float4*>(smem + OFF_E + (tid - 128) * 16) = Eg[mat * HIDV + tid - 128];
    }
    __syncthreads();

    // --- MMA mainloop (R12 verbatim) ---
    float acc[8][4];
    #pragma unroll
    for (int n = 0; n < 8; n++) {
        acc[n][0] = 0.f; acc[n][1] = 0.f; acc[n][2] = 0.f; acc[n][3] = 0.f;
    }
    int rg = w & 7, ch = w >> 3;
    int rA  = rg * 16 + (t & 7) + ((t >> 3) & 1) * 8;
    int hA  = t >> 4;
    uint32_t aAH = sb + OFF_AH + rA * 256;
    uint32_t aAL = sb + OFF_AL + rA * 256;
    uint32_t xopA = (uint32_t)(rA & 15) << 4;
    int rBoff = (t & 7) + ((t >> 4) << 3);
    int hB = (t >> 3) & 1;
    uint32_t xopB = (uint32_t)(rBoff & 15) << 4;

    #pragma unroll
    for (int k = 0; k < 8; k++) {
        uint32_t koffA = ((uint32_t)(k * 32 + hA * 16)) ^ xopA;
        uint32_t koffB = ((uint32_t)(k * 32 + hB * 16)) ^ xopB;
        uint32_t ah0, ah1, ah2, ah3, al0, al1, al2, al3;
        LDSM_X4(ah0, ah1, ah2, ah3, aAH + koffA);
        LDSM_X4(al0, al1, al2, al3, aAL + koffA);
        #pragma unroll
        for (int nt2 = 0; nt2 < 4; nt2++) {
            uint32_t bbase = (uint32_t)(ch * 64 + nt2 * 16 + rBoff) * 256 + koffB;
            uint32_t bh0, bh1, bh2, bh3, bl0, bl1, bl2, bl3;
            LDSM_X4(bh0, bh1, bh2, bh3, sb + OFF_BH + bbase);
            LDSM_X4(bl0, bl1, bl2, bl3, sb + OFF_BL + bbase);
            MMA16816(acc[nt2 * 2],     ah0, ah1, ah2, ah3, bh0, bh1);
            MMA16816(acc[nt2 * 2],     ah0, ah1, ah2, ah3, bl0, bl1);
            MMA16816(acc[nt2 * 2],     al0, al1, al2, al3, bh0, bh1);
            MMA16816(acc[nt2 * 2 + 1], ah0, ah1, ah2, ah3, bh2, bh3);
            MMA16816(acc[nt2 * 2 + 1], ah0, ah1, ah2, ah3, bl2, bl3);
            MMA16816(acc[nt2 * 2 + 1], al0, al1, al2, al3, bh2, bh3);
        }
    }

    // --- epilogue (R12 verbatim) ---
    {
        int mat_ = mat;
        int r0 = rg * 16 + (t >> 2);
        int node0 = rowbase + r0;
        int node1 = node0 + 8;
        float px0 = pos[node0 * 3], py0 = pos[node0 * 3 + 1], pz0 = pos[node0 * 3 + 2];
        float px1 = pos[node1 * 3], py1 = pos[node1 * 3 + 1], pz1 = pos[node1 * 3 + 2];
        #pragma unroll
        for (int nt = 0; nt < 8; nt++) {
            int c = ch * 64 + nt * 8 + (t & 3) * 2;
            float4 q0 = *reinterpret_cast<const float4*>(smem + OFF_Q + c * 16);
            float4 q1 = *reinterpret_cast<const float4*>(smem + OFF_Q + (c + 1) * 16);
            float4 e0 = *reinterpret_cast<const float4*>(smem + OFF_E + c * 16);
            float4 e1 = *reinterpret_cast<const float4*>(smem + OFF_E + (c + 1) * 16);
            float v00 = acc[nt][0] + px0 * q0.x + py0 * q0.y + pz0 * q0.z + q0.w;
            float v01 = acc[nt][1] + px0 * q1.x + py0 * q1.y + pz0 * q1.z + q1.w;
            float v10 = acc[nt][2] + px1 * q0.x + py1 * q0.y + pz1 * q0.z + q0.w;
            float v11 = acc[nt][3] + px1 * q1.x + py1 * q1.y + pz1 * q1.z + q1.w;
            float p00 = px0 * e0.x + py0 * e0.y + pz0 * e0.z;
            float p01 = px0 * e1.x + py0 * e1.y + pz0 * e1.z;
            float p10 = px1 * e0.x + py1 * e0.y + pz1 * e0.z;
            float p11 = px1 * e1.x + py1 * e1.y + pz1 * e1.z;
            size_t go0 = (size_t)node0 * HIDV + c;
            size_t go1 = (size_t)node1 * HIDV + c;
            if (mat_ == 0) {
                *reinterpret_cast<float2*>(u + go0) = make_float2(v00 - p00, v01 - p01);
                *reinterpret_cast<float2*>(u + go1) = make_float2(v10 - p10, v11 - p11);
            } else if (mat_ == 1) {
                *reinterpret_cast<float2*>(v + go0) = make_float2(v00 + p00, v01 + p01);
                *reinterpret_cast<float2*>(v + go1) = make_float2(v10 + p10, v11 + p11);
            } else {
                *reinterpret_cast<float2*>(l + go0) = make_float2(v00, v01);
                *reinterpret_cast<float2*>(l + go1) = make_float2(v10, v11);
            }
        }
    }
}

// ---------------------------------------------------------------------------
// x0 = latent @ lin0_W^T + lin0_b     (one warp per node)  [R12 verbatim]
// ---------------------------------------------------------------------------
__global__ void lin0_kernel(const float* __restrict__ latent,
                            const float* __restrict__ W,
                            const float* __restrict__ b,
                            float* __restrict__ xout, int N)
{
    int warp = (blockIdx.x * blockDim.x + threadIdx.x) >> 5;
    int lane = threadIdx.x & 31;
    if (warp >= N) return;
    const float* lrow = latent + warp * LATV;
    float l0 = lrow[lane], l1 = lrow[lane + 32];
    int f = lane * 4;
    float acc[4] = {0.f, 0.f, 0.f, 0.f};
    const float4* W4 = (const float4*)W;
    #pragma unroll
    for (int k4 = 0; k4 < 16; k4++) {
        float wv[4][4];
        #pragma unroll
        for (int q = 0; q < 4; q++) {
            float4 tt = W4[(f + q) * 16 + k4];
            wv[q][0] = tt.x; wv[q][1] = tt.y; wv[q][2] = tt.z; wv[q][3] = tt.w;
        }
        #pragma unroll
        for (int e = 0; e < 4; e++) {
            int k = k4 * 4 + e;
            float lv = __shfl_sync(0xffffffffu, (k < 32) ? l0 : l1, k & 31);
            #pragma unroll
            for (int q = 0; q < 4; q++) acc[q] += lv * wv[q][e];
        }
    }
    float4 o;
    o.x = acc[0] + b[f + 0];
    o.y = acc[1] + b[f + 1];
    o.z = acc[2] + b[f + 2];
    o.w = acc[3] + b[f + 3];
    *(float4*)(xout + warp * HIDV + f) = o;
}

// ---------------------------------------------------------------------------
// Fused GATv2 stencil, xl-free, with optional fused output head.  [R12 verbatim]
// ---------------------------------------------------------------------------
__global__ void gat_edge_kernel(
    const float* __restrict__ u, const float* __restrict__ v,
    const float* __restrict__ l,
    const float* __restrict__ pos,
    const float* __restrict__ att, const float* __restrict__ bias,
    const float* __restrict__ We,
    float* __restrict__ xout,
    const float* __restrict__ oW, const float* __restrict__ ob,
    float* __restrict__ fout, int N)
{
    int warp = (blockIdx.x * blockDim.x + threadIdx.x) >> 5;
    int lane = threadIdx.x & 31;
    if (warp >= N) return;
    int d = warp;
    const float4* U4 = (const float4*)u;
    const float4* V4 = (const float4*)v;
    const float4* L4 = (const float4*)l;

    float4 vd = V4[d * 32 + lane];
    float4 a4 = ((const float4*)att)[lane];

    float psx = 0.f, psy = 0.f, psz = 0.f;
    if (lane < NOFF) {
        int s = d - c_aug[lane]; if (s < 0) s += N;
        psx = pos[s * 3]; psy = pos[s * 3 + 1]; psz = pos[s * 3 + 2];
    }
    float msx = warp_sum(psx), msy = warp_sum(psy), msz = warp_sum(psz);
    float pdx = pos[d * 3], pdy = pos[d * 3 + 1], pdz = pos[d * 3 + 2];
    const float inv21 = 1.0f / 21.0f;
    float rx = pdx - msx * inv21;
    float ry = pdy - msy * inv21;
    float rz = pdz - msz * inv21;

    float wep[4][3];
    {
        int f = lane * 4;
        #pragma unroll
        for (int e = 0; e < 4; e++) {
            wep[e][0] = We[(f + e) * 3];
            wep[e][1] = We[(f + e) * 3 + 1];
            wep[e][2] = We[(f + e) * 3 + 2];
        }
    }
    float4 sc;
    sc.x = wep[0][0] * rx + wep[0][1] * ry + wep[0][2] * rz;
    sc.y = wep[1][0] * rx + wep[1][1] * ry + wep[1][2] * rz;
    sc.z = wep[2][0] * rx + wep[2][1] * ry + wep[2][2] * rz;
    sc.w = wep[3][0] * rx + wep[3][1] * ry + wep[3][2] * rz;

    if (lane == NOFF) { psx = pdx; psy = pdy; psz = pdz; }

    float4 ud = U4[d * 32 + lane];
    float a_mine = -1e30f;
    #pragma unroll
    for (int i = 0; i <= NOFF; i++) {
        float4 m;
        if (i < NOFF) {
            int s = d - c_aug[i]; if (s < 0) s += N;
            float4 us = U4[s * 32 + lane];
            m.x = us.x + vd.x; m.y = us.y + vd.y; m.z = us.z + vd.z; m.w = us.w + vd.w;
        } else {
            m.x = ud.x + vd.x + sc.x; m.y = ud.y + vd.y + sc.y;
            m.z = ud.z + vd.z + sc.z; m.w = ud.w + vd.w + sc.w;
        }
        float p = (m.x > 0.f ? m.x : 0.2f * m.x) * a4.x
                + (m.y > 0.f ? m.y : 0.2f * m.y) * a4.y
                + (m.z > 0.f ? m.z : 0.2f * m.z) * a4.z
                + (m.w > 0.f ? m.w : 0.2f * m.w) * a4.w;
        p = warp_sum(p);
        if (lane == i) a_mine = p;
    }

    float mx = warp_max(a_mine);
    float ex = (lane <= NOFF) ? __expf(a_mine - mx) : 0.f;
    float den = warp_sum(ex);
    float alpha = ex / (den + 1e-16f);

    float qx = warp_sum(alpha * psx);
    float qy = warp_sum(alpha * psy);
    float qz = warp_sum(alpha * psz);

    float4 acc = ((const float4*)bias)[lane];
    acc.x += wep[0][0] * qx + wep[0][1] * qy + wep[0][2] * qz;
    acc.y += wep[1][0] * qx + wep[1][1] * qy + wep[1][2] * qz;
    acc.z += wep[2][0] * qx + wep[2][1] * qy + wep[2][2] * qz;
    acc.w += wep[3][0] * qx + wep[3][1] * qy + wep[3][2] * qz;

    #pragma unroll
    for (int i = 0; i <= NOFF; i++) {
        float al = __shfl_sync(0xffffffffu, alpha, i);
        float4 us;
        if (i < NOFF) {
            int s = d - c_aug[i]; if (s < 0) s += N;
            us = U4[s * 32 + lane];
        } else {
            us = ud;
        }
        acc.x += al * us.x; acc.y += al * us.y;
        acc.z += al * us.z; acc.w += al * us.w;
    }

    float4 lres = L4[d * 32 + lane];
    float4 o;
    o.x = (acc.x > 0.f ? acc.x : expf(acc.x) - 1.f) + lres.x;
    o.y = (acc.y > 0.f ? acc.y : expf(acc.y) - 1.f) + lres.y;
    o.z = (acc.z > 0.f ? acc.z : expf(acc.z) - 1.f) + lres.z;
    o.w = (acc.w > 0.f ? acc.w : expf(acc.w) - 1.f) + lres.w;

    if (fout == nullptr) {
        ((float4*)xout)[d * 32 + lane] = o;
    } else {
        int f = lane * 4;
        float p0 = o.x * oW[f] + o.y * oW[f + 1] + o.z * oW[f + 2] + o.w * oW[f + 3];
        float p1 = o.x * oW[131 + f] + o.y * oW[131 + f + 1] + o.z * oW[131 + f + 2] + o.w * oW[131 + f + 3];
        float p2 = o.x * oW[262 + f] + o.y * oW[262 + f + 1] + o.z * oW[262 + f + 2] + o.w * oW[262 + f + 3];
        p0 = warp_sum(p0); p1 = warp_sum(p1); p2 = warp_sum(p2);
        if (lane == 0) {
            p0 += pdx * oW[128]       + pdy * oW[129]       + pdz * oW[130]       + ob[0];
            p1 += pdx * oW[131 + 128] + pdy * oW[131 + 129] + pdz * oW[131 + 130] + ob[1];
            p2 += pdx * oW[262 + 128] + pdy * oW[262 + 129] + pdz * oW[262 + 130] + ob[2];
            fout[d * 3] = p0; fout[d * 3 + 1] = p1; fout[d * 3 + 2] = p2;
        }
    }
}

// ---------------------------------------------------------------------------
// kNN (k=3): 8 threads per query, each scans 512 candidates, shfl merge.
// ---------------------------------------------------------------------------
__global__ void knn_find_kernel(const float* __restrict__ pos0,
                                const float* __restrict__ pos1,
                                int* __restrict__ idx, float* __restrict__ w)
{
    __shared__ float sp[N0V * 3];
    for (int i = threadIdx.x; i < N0V * 3; i += blockDim.x) sp[i] = pos0[i];
    __syncthreads();
    int tid = threadIdx.x;
    int y = blockIdx.x * 32 + (tid >> 3);
    int seg = tid & 7;
    float px = pos1[y * 3], py = pos1[y * 3 + 1], pz = pos1[y * 3 + 2];
    float d0 = 1e30f, d1 = 1e30f, d2 = 1e30f;
    int i0 = 0, i1 = 0, i2 = 0;
    int jbeg = seg * (N0V / 8), jend = jbeg + (N0V / 8);
    for (int j = jbeg; j < jend; j++) {
        float dx = px - sp[j * 3], dy = py - sp[j * 3 + 1], dz = pz - sp[j * 3 + 2];
        float dd = dx * dx + dy * dy + dz * dz;
        if (dd < d2) {
            if (dd < d1) {
                d2 = d1; i2 = i1;
                if (dd < d0) { d1 = d0; i1 = i0; d0 = dd; i0 = j; }
                else         { d1 = dd; i1 = j; }
            } else { d2 = dd; i2 = j; }
        }
    }
    #pragma unroll
    for (int off = 1; off <= 4; off <<= 1) {
        float e0 = __shfl_xor_sync(0xffffffffu, d0, off);
        float e1 = __shfl_xor_sync(0xffffffffu, d1, off);
        float e2 = __shfl_xor_sync(0xffffffffu, d2, off);
        int   j0 = __shfl_xor_sync(0xffffffffu, i0, off);
        int   j1 = __shfl_xor_sync(0xffffffffu, i1, off);
        int   j2 = __shfl_xor_sync(0xffffffffu, i2, off);
        float a[3] = {d0, d1, d2}; int ai[3] = {i0, i1, i2};
        float b[3] = {e0, e1, e2}; int bi[3] = {j0, j1, j2};
        bool mine_first = (seg & off) == 0;
        float m[3]; int mi[3];
        int pa = 0, pb = 0;
        #pragma unroll
        for (int q = 0; q < 3; q++) {
            bool ta = mine_first ? (a[pa] <= b[pb]) : (a[pa] < b[pb]);
            m[q]  = ta ? a[pa]  : b[pb];
            mi[q] = ta ? ai[pa] : bi[pb];
            pa += ta ? 1 : 0; pb += ta ? 0 : 1;
        }
        d0 = m[0]; d1 = m[1]; d2 = m[2];
        i0 = mi[0]; i1 = mi[1]; i2 = mi[2];
    }
    if (seg == 0) {
        idx[y * 3] = i0; idx[y * 3 + 1] = i1; idx[y * 3 + 2] = i2;
        w[y * 3]     = 1.f / fmaxf(d0, 1e-16f);
        w[y * 3 + 1] = 1.f / fmaxf(d1, 1e-16f);
        w[y * 3 + 2] = 1.f / fmaxf(d2, 1e-16f);
    }
}

__global__ void knn_apply_kernel(const float* __restrict__ xin,
                                 const int* __restrict__ idx,
                                 const float* __restrict__ w,
                                 float* __restrict__ xout)
{
    int y = (blockIdx.x * blockDim.x + threadIdx.x) >> 5;
    int lane = threadIdx.x & 31;
    int i0 = idx[y * 3], i1 = idx[y * 3 + 1], i2 = idx[y * 3 + 2];
    float w0 = w[y * 3], w1 = w[y * 3 + 1], w2 = w[y * 3 + 2];
    float inv = 1.f / (w0 + w1 + w2);
    const float4* X4 = (const float4*)xin;
    float4 x0 = X4[i0 * 32 + lane], x1 = X4[i1 * 32 + lane], x2 = X4[i2 * 32 + lane];
    float4 o;
    o.x = (w0 * x0.x + w1 * x1.x + w2 * x2.x) * inv;
    o.y = (w0 * x0.y + w1 * x1.y + w2 * x2.y) * inv;
    o.z = (w0 * x0.z + w1 * x1.z + w2 * x2.z) * inv;
    o.w = (w0 * x0.w + w1 * x1.w + w2 * x2.w) * inv;
    ((float4*)xout)[y * 32 + lane] = o;
}

// ---------------------------------------------------------------------------
extern "C" void kernel_launch(void* const* d_in, const int* in_sizes, int n_in,
                              void* d_out, int out_size)
{
    const float* latent    = (const float*)d_in[0];
    const float* pos0      = (const float*)d_in[1];
    const float* pos1      = (const float*)d_in[2];
    const float* conv_Wl   = (const float*)d_in[5];
    const float* conv_bl   = (const float*)d_in[6];
    const float* conv_Wr   = (const float*)d_in[7];
    const float* conv_br   = (const float*)d_in[8];
    const float* conv_We   = (const float*)d_in[9];
    const float* conv_att  = (const float*)d_in[10];
    const float* conv_bias = (const float*)d_in[11];
    const float* lin0_W    = (const float*)d_in[12];
    const float* lin0_b    = (const float*)d_in[13];
    const float* lins_W    = (const float*)d_in[14];
    const float* lins_b    = (const float*)d_in[15];
    const float* out_W     = (const float*)d_in[16];
    const float* out_b     = (const float*)d_in[17];

    float *xa, *xb, *u, *v, *l, *w;
    int* idx;
    uint4 *wsh, *wsl;
    float4 *Qg, *Eg;
    cudaGetSymbolAddress((void**)&xa,  g_xa);
    cudaGetSymbolAddress((void**)&xb,  g_xb);
    cudaGetSymbolAddress((void**)&u,   g_u);
    cudaGetSymbolAddress((void**)&v,   g_v);
    cudaGetSymbolAddress((void**)&l,   g_l);
    cudaGetSymbolAddress((void**)&idx, g_idx);
    cudaGetSymbolAddress((void**)&w,   g_w);
    cudaGetSymbolAddress((void**)&wsh, g_wswh);
    cudaGetSymbolAddress((void**)&wsl, g_wswl);
    cudaGetSymbolAddress((void**)&Qg,  g_Q);
    cudaGetSymbolAddress((void**)&Eg,  g_E);

    cudaFuncSetAttribute(gemm_mma_kernel,
                         cudaFuncAttributeMaxDynamicSharedMemorySize, GSMEM_TOTAL);

    prep_weights_kernel<<<12, 256>>>(conv_Wl, conv_Wr, lins_W,
                                     conv_bl, conv_br, lins_b, conv_We);
    lin0_kernel<<<N0V / 8, 256>>>(latent, lin0_W, lin0_b, xa, N0V);

    for (int c = 0; c < 2; c++) {
        gemm_mma_kernel<<<dim3(N0V / 128, 3), 512, GSMEM_TOTAL>>>(
            xa, pos0,
            wsh + (size_t)(c * 3) * 2048, wsl + (size_t)(c * 3) * 2048,
            Qg + c * 3 * HIDV, Eg + c * 3 * HIDV,
            u, v, l);
        gat_edge_kernel<<<N0V / 8, 256>>>(
            u, v, l, pos0,
            conv_att + c * HIDV, conv_bias + c * HIDV, conv_We + c * HIDV * 3,
            xa, nullptr, nullptr, nullptr, N0V);
    }

    knn_find_kernel<<<N1V / 32, 256>>>(pos0, pos1, idx, w);
    knn_apply_kernel<<<N1V / 8, 256>>>(xa, idx, w, xb);

    for (int c = 2; c < 4; c++) {
        gemm_mma_kernel<<<dim3(N1V / 128, 3), 512, GSMEM_TOTAL>>>(
            xb, pos1,
            wsh + (size_t)(c * 3) * 2048, wsl + (size_t)(c * 3) * 2048,
            Qg + c * 3 * HIDV, Eg + c * 3 * HIDV,
            u, v, l);
        if (c == 3) {
            gat_edge_kernel<<<N1V / 8, 256>>>(
                u, v, l, pos1,
                conv_att + c * HIDV, conv_bias + c * HIDV, conv_We + c * HIDV * 3,
                nullptr, out_W, out_b, (float*)d_out, N1V);
        } else {
            gat_edge_kernel<<<N1V / 8, 256>>>(
                u, v, l, pos1,
                conv_att + c * HIDV, conv_bias + c * HIDV, conv_We + c * HIDV * 3,
                xb, nullptr, nullptr, nullptr, N1V);
        }
    }
}

// round 14
// speedup vs baseline: 1.0920x; 1.0920x over previous
#include <cuda_runtime.h>
#include <cuda_bf16.h>
#include <math.h>
#include <stdint.h>

#define N0V 4096
#define N1V 16384
#define HIDV 128
#define LATV 64
#define NOFF 21

__constant__ int c_aug[NOFF] = {1,2,3,4,5,6,7,8,9,10,11,12,13,14,15,16,17,18,19,21,24};

// scratch (static device globals; allocation-free)
__device__ float g_xa[N1V * HIDV];
__device__ float g_xb[N1V * HIDV];
__device__ float g_u [N1V * HIDV];
__device__ float g_v [N1V * HIDV];
__device__ float g_l [N1V * HIDV];
__device__ int   g_idx[N1V * 3];
__device__ float g_w  [N1V * 3];

__device__ __forceinline__ float warp_sum(float x) {
    #pragma unroll
    for (int o = 16; o; o >>= 1) x += __shfl_xor_sync(0xffffffffu, x, o);
    return x;
}
__device__ __forceinline__ float warp_max(float x) {
    #pragma unroll
    for (int o = 16; o; o >>= 1) x = fmaxf(x, __shfl_xor_sync(0xffffffffu, x, o));
    return x;
}

__device__ __forceinline__ uint32_t smem_u32(const void* p) {
    uint32_t a;
    asm("{ .reg .u64 t; cvta.to.shared.u64 t, %1; cvt.u32.u64 %0, t; }"
        : "=r"(a) : "l"(p));
    return a;
}

#define LDSM_X4(r0, r1, r2, r3, addr) \
    asm volatile("ldmatrix.sync.aligned.m8n8.x4.shared.b16 {%0,%1,%2,%3}, [%4];" \
                 : "=r"(r0), "=r"(r1), "=r"(r2), "=r"(r3) : "r"(addr))

#define MMA16816(d, a0, a1, a2, a3, b0, b1) \
    asm volatile("mma.sync.aligned.m16n8k16.row.col.f32.bf16.bf16.f32 " \
                 "{%0,%1,%2,%3}, {%4,%5,%6,%7}, {%8,%9}, {%0,%1,%2,%3};" \
                 : "+f"((d)[0]), "+f"((d)[1]), "+f"((d)[2]), "+f"((d)[3]) \
                 : "r"(a0), "r"(a1), "r"(a2), "r"(a3), "r"(b0), "r"(b1))

__device__ __forceinline__ void cvt_pair(float a, float b, uint32_t& hi, uint32_t& lo) {
    __nv_bfloat16 ha = __float2bfloat16(a), hb = __float2bfloat16(b);
    float ra = a - __bfloat162float(ha);
    float rb = b - __bfloat162float(hb);
    __nv_bfloat162 h2 = __halves2bfloat162(ha, hb);
    __nv_bfloat162 l2 = __halves2bfloat162(__float2bfloat16(ra), __float2bfloat16(rb));
    hi = *reinterpret_cast<uint32_t*>(&h2);
    lo = *reinterpret_cast<uint32_t*>(&l2);
}

// ===========================================================================
// HMMA layer GEMM — 256 threads, tile 128 rows x 64 cols, R12 mainloop,
// in-kernel fp32->bf16 hi/lo conversion (trusted path).
// grid (N/128, 6): mat = y>>1, col half = y&1. ~98KB smem -> 2 blocks/SM.
// mat-0 epilogue writes only u = xl - pos@We^T.
// ===========================================================================
#define OFF_AH 0
#define OFF_AL 32768
#define OFF_BH 65536
#define OFF_BL 81920
#define OFF_Q  98304
#define OFF_E  99328
#define GSMEM_TOTAL 100352

__global__ void __launch_bounds__(256) gemm_mma_kernel(
    const float* __restrict__ x, const float* __restrict__ pos,
    const float* __restrict__ Wl, const float* __restrict__ bl,
    const float* __restrict__ Wr, const float* __restrict__ br,
    const float* __restrict__ We,
    const float* __restrict__ Lw, const float* __restrict__ lb,
    float* __restrict__ u, float* __restrict__ v, float* __restrict__ l)
{
    extern __shared__ char smem[];
    uint32_t sb = smem_u32(smem);
    int tid = threadIdx.x;
    int w = tid >> 5, t = tid & 31;
    int mat = blockIdx.y >> 1;
    int cbase = (blockIdx.y & 1) * 64;
    int rowbase = blockIdx.x * 128;
    const float* W    = (mat == 0) ? Wl : (mat == 1) ? Wr : Lw;
    const float* bias = (mat == 0) ? bl : (mat == 1) ? br : lb;

    // --- convert X tile -> A_hi/A_lo: row r = tid>>1, half part = tid&1 ---
    {
        int r = tid >> 1, part = tid & 1;
        const float4* xr = (const float4*)(x + (size_t)(rowbase + r) * HIDV + part * 64);
        char* bH = smem + OFF_AH + r * 256;
        char* bL = smem + OFF_AL + r * 256;
        uint32_t xop = (uint32_t)(r & 15) << 4;
        #pragma unroll
        for (int j = 0; j < 8; j++) {
            float4 v0 = xr[j * 2], v1 = xr[j * 2 + 1];
            uint32_t h0, l0, h1, l1, h2, l2, h3, l3;
            cvt_pair(v0.x, v0.y, h0, l0); cvt_pair(v0.z, v0.w, h1, l1);
            cvt_pair(v1.x, v1.y, h2, l2); cvt_pair(v1.z, v1.w, h3, l3);
            uint32_t off = ((uint32_t)(part * 128 + j * 16)) ^ xop;
            *reinterpret_cast<uint4*>(bH + off) = make_uint4(h0, h1, h2, h3);
            *reinterpret_cast<uint4*>(bL + off) = make_uint4(l0, l1, l2, l3);
        }
    }
    // --- convert W cols [cbase, cbase+64) -> B_hi/B_lo: c = tid>>2, q = tid&3 ---
    {
        int c = tid >> 2, q = tid & 3;
        const float* wr = W + (cbase + c) * 131 + q * 32;
        char* bH = smem + OFF_BH + c * 256;
        char* bL = smem + OFF_BL + c * 256;
        uint32_t xop = (uint32_t)(c & 15) << 4;
        #pragma unroll
        for (int j = 0; j < 4; j++) {
            float f0 = wr[j * 8 + 0], f1 = wr[j * 8 + 1], f2 = wr[j * 8 + 2], f3 = wr[j * 8 + 3];
            float f4 = wr[j * 8 + 4], f5 = wr[j * 8 + 5], f6 = wr[j * 8 + 6], f7 = wr[j * 8 + 7];
            uint32_t h0, l0, h1, l1, h2, l2, h3, l3;
            cvt_pair(f0, f1, h0, l0); cvt_pair(f2, f3, h1, l1);
            cvt_pair(f4, f5, h2, l2); cvt_pair(f6, f7, h3, l3);
            uint32_t off = ((uint32_t)(q * 64 + j * 16)) ^ xop;
            *reinterpret_cast<uint4*>(bH + off) = make_uint4(h0, h1, h2, h3);
            *reinterpret_cast<uint4*>(bL + off) = make_uint4(l0, l1, l2, l3);
        }
    }
    // --- epilogue tables for this col half ---
    if (tid < 64) {
        int c = cbase + tid;
        float4 q = make_float4(W[c * 131 + 128], W[c * 131 + 129], W[c * 131 + 130], bias[c]);
        *reinterpret_cast<float4*>(smem + OFF_Q + tid * 16) = q;
    } else if (tid < 128) {
        int c = cbase + tid - 64;
        float4 e = (mat < 2)
            ? make_float4(We[c * 3], We[c * 3 + 1], We[c * 3 + 2], 0.f)
            : make_float4(0.f, 0.f, 0.f, 0.f);
        *reinterpret_cast<float4*>(smem + OFF_E + (tid - 64) * 16) = e;
    }
    __syncthreads();

    // --- MMA mainloop (R12 structure; 8 warps, warp = 16 rows x 64 cols) ---
    float acc[8][4];
    #pragma unroll
    for (int n = 0; n < 8; n++) {
        acc[n][0] = 0.f; acc[n][1] = 0.f; acc[n][2] = 0.f; acc[n][3] = 0.f;
    }
    int rA  = w * 16 + (t & 7) + ((t >> 3) & 1) * 8;
    int hA  = t >> 4;
    uint32_t aAH = sb + OFF_AH + rA * 256;
    uint32_t aAL = sb + OFF_AL + rA * 256;
    uint32_t xopA = (uint32_t)(rA & 15) << 4;
    int rBoff = (t & 7) + ((t >> 4) << 3);
    int hB = (t >> 3) & 1;
    uint32_t xopB = (uint32_t)(rBoff & 15) << 4;

    #pragma unroll
    for (int k = 0; k < 8; k++) {
        uint32_t koffA = ((uint32_t)(k * 32 + hA * 16)) ^ xopA;
        uint32_t koffB = ((uint32_t)(k * 32 + hB * 16)) ^ xopB;
        uint32_t ah0, ah1, ah2, ah3, al0, al1, al2, al3;
        LDSM_X4(ah0, ah1, ah2, ah3, aAH + koffA);
        LDSM_X4(al0, al1, al2, al3, aAL + koffA);
        #pragma unroll
        for (int nt2 = 0; nt2 < 4; nt2++) {
            uint32_t bbase = (uint32_t)(nt2 * 16 + rBoff) * 256 + koffB;
            uint32_t bh0, bh1, bh2, bh3, bl0, bl1, bl2, bl3;
            LDSM_X4(bh0, bh1, bh2, bh3, sb + OFF_BH + bbase);
            LDSM_X4(bl0, bl1, bl2, bl3, sb + OFF_BL + bbase);
            MMA16816(acc[nt2 * 2],     ah0, ah1, ah2, ah3, bh0, bh1);
            MMA16816(acc[nt2 * 2],     ah0, ah1, ah2, ah3, bl0, bl1);
            MMA16816(acc[nt2 * 2],     al0, al1, al2, al3, bh0, bh1);
            MMA16816(acc[nt2 * 2 + 1], ah0, ah1, ah2, ah3, bh2, bh3);
            MMA16816(acc[nt2 * 2 + 1], ah0, ah1, ah2, ah3, bl2, bl3);
            MMA16816(acc[nt2 * 2 + 1], al0, al1, al2, al3, bh2, bh3);
        }
    }

    // --- epilogue ---
    {
        int mat_ = mat;
        int r0 = w * 16 + (t >> 2);
        int node0 = rowbase + r0;
        int node1 = node0 + 8;
        float px0 = pos[node0 * 3], py0 = pos[node0 * 3 + 1], pz0 = pos[node0 * 3 + 2];
        float px1 = pos[node1 * 3], py1 = pos[node1 * 3 + 1], pz1 = pos[node1 * 3 + 2];
        #pragma unroll
        for (int nt = 0; nt < 8; nt++) {
            int cl = nt * 8 + (t & 3) * 2;    // col within 64-col half
            float4 q0 = *reinterpret_cast<const float4*>(smem + OFF_Q + cl * 16);
            float4 q1 = *reinterpret_cast<const float4*>(smem + OFF_Q + (cl + 1) * 16);
            float4 e0 = *reinterpret_cast<const float4*>(smem + OFF_E + cl * 16);
            float4 e1 = *reinterpret_cast<const float4*>(smem + OFF_E + (cl + 1) * 16);
            float v00 = acc[nt][0] + px0 * q0.x + py0 * q0.y + pz0 * q0.z + q0.w;
            float v01 = acc[nt][1] + px0 * q1.x + py0 * q1.y + pz0 * q1.z + q1.w;
            float v10 = acc[nt][2] + px1 * q0.x + py1 * q0.y + pz1 * q0.z + q0.w;
            float v11 = acc[nt][3] + px1 * q1.x + py1 * q1.y + pz1 * q1.z + q1.w;
            float p00 = px0 * e0.x + py0 * e0.y + pz0 * e0.z;
            float p01 = px0 * e1.x + py0 * e1.y + pz0 * e1.z;
            float p10 = px1 * e0.x + py1 * e0.y + pz1 * e0.z;
            float p11 = px1 * e1.x + py1 * e1.y + pz1 * e1.z;
            size_t go0 = (size_t)node0 * HIDV + cbase + cl;
            size_t go1 = (size_t)node1 * HIDV + cbase + cl;
            if (mat_ == 0) {
                *reinterpret_cast<float2*>(u + go0) = make_float2(v00 - p00, v01 - p01);
                *reinterpret_cast<float2*>(u + go1) = make_float2(v10 - p10, v11 - p11);
            } else if (mat_ == 1) {
                *reinterpret_cast<float2*>(v + go0) = make_float2(v00 + p00, v01 + p01);
                *reinterpret_cast<float2*>(v + go1) = make_float2(v10 + p10, v11 + p11);
            } else {
                *reinterpret_cast<float2*>(l + go0) = make_float2(v00, v01);
                *reinterpret_cast<float2*>(l + go1) = make_float2(v10, v11);
            }
        }
    }
}

// ---------------------------------------------------------------------------
// x0 = latent @ lin0_W^T + lin0_b     (one warp per node)  [R12 verbatim]
// ---------------------------------------------------------------------------
__global__ void lin0_kernel(const float* __restrict__ latent,
                            const float* __restrict__ W,
                            const float* __restrict__ b,
                            float* __restrict__ xout, int N)
{
    int warp = (blockIdx.x * blockDim.x + threadIdx.x) >> 5;
    int lane = threadIdx.x & 31;
    if (warp >= N) return;
    const float* lrow = latent + warp * LATV;
    float l0 = lrow[lane], l1 = lrow[lane + 32];
    int f = lane * 4;
    float acc[4] = {0.f, 0.f, 0.f, 0.f};
    const float4* W4 = (const float4*)W;
    #pragma unroll
    for (int k4 = 0; k4 < 16; k4++) {
        float wv[4][4];
        #pragma unroll
        for (int q = 0; q < 4; q++) {
            float4 tt = W4[(f + q) * 16 + k4];
            wv[q][0] = tt.x; wv[q][1] = tt.y; wv[q][2] = tt.z; wv[q][3] = tt.w;
        }
        #pragma unroll
        for (int e = 0; e < 4; e++) {
            int k = k4 * 4 + e;
            float lv = __shfl_sync(0xffffffffu, (k < 32) ? l0 : l1, k & 31);
            #pragma unroll
            for (int q = 0; q < 4; q++) acc[q] += lv * wv[q][e];
        }
    }
    float4 o;
    o.x = acc[0] + b[f + 0];
    o.y = acc[1] + b[f + 1];
    o.z = acc[2] + b[f + 2];
    o.w = acc[3] + b[f + 3];
    *(float4*)(xout + warp * HIDV + f) = o;
}

// ---------------------------------------------------------------------------
// Fused GATv2 stencil, xl-free, with optional fused output head.  [R12 verbatim]
// ---------------------------------------------------------------------------
__global__ void gat_edge_kernel(
    const float* __restrict__ u, const float* __restrict__ v,
    const float* __restrict__ l,
    const float* __restrict__ pos,
    const float* __restrict__ att, const float* __restrict__ bias,
    const float* __restrict__ We,
    float* __restrict__ xout,
    const float* __restrict__ oW, const float* __restrict__ ob,
    float* __restrict__ fout, int N)
{
    int warp = (blockIdx.x * blockDim.x + threadIdx.x) >> 5;
    int lane = threadIdx.x & 31;
    if (warp >= N) return;
    int d = warp;
    const float4* U4 = (const float4*)u;
    const float4* V4 = (const float4*)v;
    const float4* L4 = (const float4*)l;

    float4 vd = V4[d * 32 + lane];
    float4 a4 = ((const float4*)att)[lane];

    float psx = 0.f, psy = 0.f, psz = 0.f;
    if (lane < NOFF) {
        int s = d - c_aug[lane]; if (s < 0) s += N;
        psx = pos[s * 3]; psy = pos[s * 3 + 1]; psz = pos[s * 3 + 2];
    }
    float msx = warp_sum(psx), msy = warp_sum(psy), msz = warp_sum(psz);
    float pdx = pos[d * 3], pdy = pos[d * 3 + 1], pdz = pos[d * 3 + 2];
    const float inv21 = 1.0f / 21.0f;
    float rx = pdx - msx * inv21;
    float ry = pdy - msy * inv21;
    float rz = pdz - msz * inv21;

    float wep[4][3];
    {
        int f = lane * 4;
        #pragma unroll
        for (int e = 0; e < 4; e++) {
            wep[e][0] = We[(f + e) * 3];
            wep[e][1] = We[(f + e) * 3 + 1];
            wep[e][2] = We[(f + e) * 3 + 2];
        }
    }
    float4 sc;
    sc.x = wep[0][0] * rx + wep[0][1] * ry + wep[0][2] * rz;
    sc.y = wep[1][0] * rx + wep[1][1] * ry + wep[1][2] * rz;
    sc.z = wep[2][0] * rx + wep[2][1] * ry + wep[2][2] * rz;
    sc.w = wep[3][0] * rx + wep[3][1] * ry + wep[3][2] * rz;

    if (lane == NOFF) { psx = pdx; psy = pdy; psz = pdz; }

    float4 ud = U4[d * 32 + lane];
    float a_mine = -1e30f;
    #pragma unroll
    for (int i = 0; i <= NOFF; i++) {
        float4 m;
        if (i < NOFF) {
            int s = d - c_aug[i]; if (s < 0) s += N;
            float4 us = U4[s * 32 + lane];
            m.x = us.x + vd.x; m.y = us.y + vd.y; m.z = us.z + vd.z; m.w = us.w + vd.w;
        } else {
            m.x = ud.x + vd.x + sc.x; m.y = ud.y + vd.y + sc.y;
            m.z = ud.z + vd.z + sc.z; m.w = ud.w + vd.w + sc.w;
        }
        float p = (m.x > 0.f ? m.x : 0.2f * m.x) * a4.x
                + (m.y > 0.f ? m.y : 0.2f * m.y) * a4.y
                + (m.z > 0.f ? m.z : 0.2f * m.z) * a4.z
                + (m.w > 0.f ? m.w : 0.2f * m.w) * a4.w;
        p = warp_sum(p);
        if (lane == i) a_mine = p;
    }

    float mx = warp_max(a_mine);
    float ex = (lane <= NOFF) ? __expf(a_mine - mx) : 0.f;
    float den = warp_sum(ex);
    float alpha = ex / (den + 1e-16f);

    float qx = warp_sum(alpha * psx);
    float qy = warp_sum(alpha * psy);
    float qz = warp_sum(alpha * psz);

    float4 acc = ((const float4*)bias)[lane];
    acc.x += wep[0][0] * qx + wep[0][1] * qy + wep[0][2] * qz;
    acc.y += wep[1][0] * qx + wep[1][1] * qy + wep[1][2] * qz;
    acc.z += wep[2][0] * qx + wep[2][1] * qy + wep[2][2] * qz;
    acc.w += wep[3][0] * qx + wep[3][1] * qy + wep[3][2] * qz;

    #pragma unroll
    for (int i = 0; i <= NOFF; i++) {
        float al = __shfl_sync(0xffffffffu, alpha, i);
        float4 us;
        if (i < NOFF) {
            int s = d - c_aug[i]; if (s < 0) s += N;
            us = U4[s * 32 + lane];
        } else {
            us = ud;
        }
        acc.x += al * us.x; acc.y += al * us.y;
        acc.z += al * us.z; acc.w += al * us.w;
    }

    float4 lres = L4[d * 32 + lane];
    float4 o;
    o.x = (acc.x > 0.f ? acc.x : expf(acc.x) - 1.f) + lres.x;
    o.y = (acc.y > 0.f ? acc.y : expf(acc.y) - 1.f) + lres.y;
    o.z = (acc.z > 0.f ? acc.z : expf(acc.z) - 1.f) + lres.z;
    o.w = (acc.w > 0.f ? acc.w : expf(acc.w) - 1.f) + lres.w;

    if (fout == nullptr) {
        ((float4*)xout)[d * 32 + lane] = o;
    } else {
        int f = lane * 4;
        float p0 = o.x * oW[f] + o.y * oW[f + 1] + o.z * oW[f + 2] + o.w * oW[f + 3];
        float p1 = o.x * oW[131 + f] + o.y * oW[131 + f + 1] + o.z * oW[131 + f + 2] + o.w * oW[131 + f + 3];
        float p2 = o.x * oW[262 + f] + o.y * oW[262 + f + 1] + o.z * oW[262 + f + 2] + o.w * oW[262 + f + 3];
        p0 = warp_sum(p0); p1 = warp_sum(p1); p2 = warp_sum(p2);
        if (lane == 0) {
            p0 += pdx * oW[128]       + pdy * oW[129]       + pdz * oW[130]       + ob[0];
            p1 += pdx * oW[131 + 128] + pdy * oW[131 + 129] + pdz * oW[131 + 130] + ob[1];
            p2 += pdx * oW[262 + 128] + pdy * oW[262 + 129] + pdz * oW[262 + 130] + ob[2];
            fout[d * 3] = p0; fout[d * 3 + 1] = p1; fout[d * 3 + 2] = p2;
        }
    }
}

// ---------------------------------------------------------------------------
// kNN (k=3): 4 threads per query, each scans 1024 candidates.  [R12 verbatim]
// ---------------------------------------------------------------------------
__global__ void knn_find_kernel(const float* __restrict__ pos0,
                                const float* __restrict__ pos1,
                                int* __restrict__ idx, float* __restrict__ w)
{
    __shared__ float sp[N0V * 3];
    for (int i = threadIdx.x; i < N0V * 3; i += blockDim.x) sp[i] = pos0[i];
    __syncthreads();
    int tid = threadIdx.x;
    int y = blockIdx.x * 64 + (tid >> 2);
    int seg = tid & 3;
    float px = pos1[y * 3], py = pos1[y * 3 + 1], pz = pos1[y * 3 + 2];
    float d0 = 1e30f, d1 = 1e30f, d2 = 1e30f;
    int i0 = 0, i1 = 0, i2 = 0;
    int jbeg = seg * (N0V / 4), jend = jbeg + (N0V / 4);
    for (int j = jbeg; j < jend; j++) {
        float dx = px - sp[j * 3], dy = py - sp[j * 3 + 1], dz = pz - sp[j * 3 + 2];
        float dd = dx * dx + dy * dy + dz * dz;
        if (dd < d2) {
            if (dd < d1) {
                d2 = d1; i2 = i1;
                if (dd < d0) { d1 = d0; i1 = i0; d0 = dd; i0 = j; }
                else         { d1 = dd; i1 = j; }
            } else { d2 = dd; i2 = j; }
        }
    }
    #pragma unroll
    for (int off = 1; off <= 2; off <<= 1) {
        float e0 = __shfl_xor_sync(0xffffffffu, d0, off);
        float e1 = __shfl_xor_sync(0xffffffffu, d1, off);
        float e2 = __shfl_xor_sync(0xffffffffu, d2, off);
        int   j0 = __shfl_xor_sync(0xffffffffu, i0, off);
        int   j1 = __shfl_xor_sync(0xffffffffu, i1, off);
        int   j2 = __shfl_xor_sync(0xffffffffu, i2, off);
        float a[3] = {d0, d1, d2}; int ai[3] = {i0, i1, i2};
        float b[3] = {e0, e1, e2}; int bi[3] = {j0, j1, j2};
        bool mine_first = (seg & off) == 0;
        float m[3]; int mi[3];
        int pa = 0, pb = 0;
        #pragma unroll
        for (int q = 0; q < 3; q++) {
            bool ta = mine_first ? (a[pa] <= b[pb]) : (a[pa] < b[pb]);
            m[q]  = ta ? a[pa]  : b[pb];
            mi[q] = ta ? ai[pa] : bi[pb];
            pa += ta ? 1 : 0; pb += ta ? 0 : 1;
        }
        d0 = m[0]; d1 = m[1]; d2 = m[2];
        i0 = mi[0]; i1 = mi[1]; i2 = mi[2];
    }
    if (seg == 0) {
        idx[y * 3] = i0; idx[y * 3 + 1] = i1; idx[y * 3 + 2] = i2;
        w[y * 3]     = 1.f / fmaxf(d0, 1e-16f);
        w[y * 3 + 1] = 1.f / fmaxf(d1, 1e-16f);
        w[y * 3 + 2] = 1.f / fmaxf(d2, 1e-16f);
    }
}

__global__ void knn_apply_kernel(const float* __restrict__ xin,
                                 const int* __restrict__ idx,
                                 const float* __restrict__ w,
                                 float* __restrict__ xout)
{
    int y = (blockIdx.x * blockDim.x + threadIdx.x) >> 5;
    int lane = threadIdx.x & 31;
    int i0 = idx[y * 3], i1 = idx[y * 3 + 1], i2 = idx[y * 3 + 2];
    float w0 = w[y * 3], w1 = w[y * 3 + 1], w2 = w[y * 3 + 2];
    float inv = 1.f / (w0 + w1 + w2);
    const float4* X4 = (const float4*)xin;
    float4 x0 = X4[i0 * 32 + lane], x1 = X4[i1 * 32 + lane], x2 = X4[i2 * 32 + lane];
    float4 o;
    o.x = (w0 * x0.x + w1 * x1.x + w2 * x2.x) * inv;
    o.y = (w0 * x0.y + w1 * x1.y + w2 * x2.y) * inv;
    o.z = (w0 * x0.z + w1 * x1.z + w2 * x2.z) * inv;
    o.w = (w0 * x0.w + w1 * x1.w + w2 * x2.w) * inv;
    ((float4*)xout)[y * 32 + lane] = o;
}

// ---------------------------------------------------------------------------
extern "C" void kernel_launch(void* const* d_in, const int* in_sizes, int n_in,
                              void* d_out, int out_size)
{
    const float* latent    = (const float*)d_in[0];
    const float* pos0      = (const float*)d_in[1];
    const float* pos1      = (const float*)d_in[2];
    const float* conv_Wl   = (const float*)d_in[5];
    const float* conv_bl   = (const float*)d_in[6];
    const float* conv_Wr   = (const float*)d_in[7];
    const float* conv_br   = (const float*)d_in[8];
    const float* conv_We   = (const float*)d_in[9];
    const float* conv_att  = (const float*)d_in[10];
    const float* conv_bias = (const float*)d_in[11];
    const float* lin0_W    = (const float*)d_in[12];
    const float* lin0_b    = (const float*)d_in[13];
    const float* lins_W    = (const float*)d_in[14];
    const float* lins_b    = (const float*)d_in[15];
    const float* out_W     = (const float*)d_in[16];
    const float* out_b     = (const float*)d_in[17];

    float *xa, *xb, *u, *v, *l, *w;
    int* idx;
    cudaGetSymbolAddress((void**)&xa,  g_xa);
    cudaGetSymbolAddress((void**)&xb,  g_xb);
    cudaGetSymbolAddress((void**)&u,   g_u);
    cudaGetSymbolAddress((void**)&v,   g_v);
    cudaGetSymbolAddress((void**)&l,   g_l);
    cudaGetSymbolAddress((void**)&idx, g_idx);
    cudaGetSymbolAddress((void**)&w,   g_w);

    cudaFuncSetAttribute(gemm_mma_kernel,
                         cudaFuncAttributeMaxDynamicSharedMemorySize, GSMEM_TOTAL);

    lin0_kernel<<<N0V / 8, 256>>>(latent, lin0_W, lin0_b, xa, N0V);

    for (int c = 0; c < 2; c++) {
        gemm_mma_kernel<<<dim3(N0V / 128, 6), 256, GSMEM_TOTAL>>>(
            xa, pos0,
            conv_Wl + c * HIDV * 131, conv_bl + c * HIDV,
            conv_Wr + c * HIDV * 131, conv_br + c * HIDV,
            conv_We + c * HIDV * 3,
            lins_W + c * HIDV * 131, lins_b + c * HIDV,
            u, v, l);
        gat_edge_kernel<<<N0V / 8, 256>>>(
            u, v, l, pos0,
            conv_att + c * HIDV, conv_bias + c * HIDV, conv_We + c * HIDV * 3,
            xa, nullptr, nullptr, nullptr, N0V);
    }

    knn_find_kernel<<<N1V / 64, 256>>>(pos0, pos1, idx, w);
    knn_apply_kernel<<<N1V / 8, 256>>>(xa, idx, w, xb);

    for (int c = 2; c < 4; c++) {
        gemm_mma_kernel<<<dim3(N1V / 128, 6), 256, GSMEM_TOTAL>>>(
            xb, pos1,
            conv_Wl + c * HIDV * 131, conv_bl + c * HIDV,
            conv_Wr + c * HIDV * 131, conv_br + c * HIDV,
            conv_We + c * HIDV * 3,
            lins_W + c * HIDV * 131, lins_b + c * HIDV,
            u, v, l);
        if (c == 3) {
            gat_edge_kernel<<<N1V / 8, 256>>>(
                u, v, l, pos1,
                conv_att + c * HIDV, conv_bias + c * HIDV, conv_We + c * HIDV * 3,
                nullptr, out_W, out_b, (float*)d_out, N1V);
        } else {
            gat_edge_kernel<<<N1V / 8, 256>>>(
                u, v, l, pos1,
                conv_att + c * HIDV, conv_bias + c * HIDV, conv_We + c * HIDV * 3,
                xb, nullptr, nullptr, nullptr, N1V);
        }
    }
}

// round 15
// speedup vs baseline: 1.2577x; 1.1518x over previous
#include <cuda_runtime.h>
#include <cuda_bf16.h>
#include <math.h>
#include <stdint.h>

#define N0V 4096
#define N1V 16384
#define HIDV 128
#define LATV 64
#define NOFF 21

__constant__ int c_aug[NOFF] = {1,2,3,4,5,6,7,8,9,10,11,12,13,14,15,16,17,18,19,21,24};

// scratch (static device globals; allocation-free)
__device__ float g_xa[N1V * HIDV];
__device__ float g_xb[N1V * HIDV];
__device__ float g_u [N1V * HIDV];
__device__ float g_v [N1V * HIDV];
__device__ float g_l [N1V * HIDV];
__device__ int   g_idx[N1V * 3];
__device__ float g_w  [N1V * 3];

__device__ __forceinline__ float warp_sum(float x) {
    #pragma unroll
    for (int o = 16; o; o >>= 1) x += __shfl_xor_sync(0xffffffffu, x, o);
    return x;
}
__device__ __forceinline__ float warp_max(float x) {
    #pragma unroll
    for (int o = 16; o; o >>= 1) x = fmaxf(x, __shfl_xor_sync(0xffffffffu, x, o));
    return x;
}

__device__ __forceinline__ uint32_t smem_u32(const void* p) {
    uint32_t a;
    asm("{ .reg .u64 t; cvta.to.shared.u64 t, %1; cvt.u32.u64 %0, t; }"
        : "=r"(a) : "l"(p));
    return a;
}

#define LDSM_X4(r0, r1, r2, r3, addr) \
    asm volatile("ldmatrix.sync.aligned.m8n8.x4.shared.b16 {%0,%1,%2,%3}, [%4];" \
                 : "=r"(r0), "=r"(r1), "=r"(r2), "=r"(r3) : "r"(addr))

#define MMA16816(d, a0, a1, a2, a3, b0, b1) \
    asm volatile("mma.sync.aligned.m16n8k16.row.col.f32.bf16.bf16.f32 " \
                 "{%0,%1,%2,%3}, {%4,%5,%6,%7}, {%8,%9}, {%0,%1,%2,%3};" \
                 : "+f"((d)[0]), "+f"((d)[1]), "+f"((d)[2]), "+f"((d)[3]) \
                 : "r"(a0), "r"(a1), "r"(a2), "r"(a3), "r"(b0), "r"(b1))

__device__ __forceinline__ void cvt_pair(float a, float b, uint32_t& hi, uint32_t& lo) {
    __nv_bfloat16 ha = __float2bfloat16(a), hb = __float2bfloat16(b);
    float ra = a - __bfloat162float(ha);
    float rb = b - __bfloat162float(hb);
    __nv_bfloat162 h2 = __halves2bfloat162(ha, hb);
    __nv_bfloat162 l2 = __halves2bfloat162(__float2bfloat16(ra), __float2bfloat16(rb));
    hi = *reinterpret_cast<uint32_t*>(&h2);
    lo = *reinterpret_cast<uint32_t*>(&l2);
}

// ===========================================================================
// HMMA layer GEMM (R12 verbatim: 512 threads, 128x128 tile, grid (N/128, 3);
// mat-0 epilogue writes only u = xl - pos@We^T).
// ===========================================================================
#define OFF_AH 0
#define OFF_AL 32768
#define OFF_BH 65536
#define OFF_BL 98304
#define OFF_Q  131072
#define OFF_E  133120
#define GSMEM_TOTAL 135168

__global__ void __launch_bounds__(512, 1) gemm_mma_kernel(
    const float* __restrict__ x, const float* __restrict__ pos,
    const float* __restrict__ Wl, const float* __restrict__ bl,
    const float* __restrict__ Wr, const float* __restrict__ br,
    const float* __restrict__ We,
    const float* __restrict__ Lw, const float* __restrict__ lb,
    float* __restrict__ u, float* __restrict__ v, float* __restrict__ l)
{
    extern __shared__ char smem[];
    uint32_t sb = smem_u32(smem);
    int tid = threadIdx.x;
    int w = tid >> 5, t = tid & 31;
    int mat = blockIdx.y;
    int rowbase = blockIdx.x * 128;
    const float* W    = (mat == 0) ? Wl : (mat == 1) ? Wr : Lw;
    const float* bias = (mat == 0) ? bl : (mat == 1) ? br : lb;

    {
        int r = tid >> 2, q = tid & 3;
        const float4* xr = (const float4*)(x + (size_t)(rowbase + r) * HIDV + q * 32);
        char* bH = smem + OFF_AH + r * 256;
        char* bL = smem + OFF_AL + r * 256;
        uint32_t xop = (uint32_t)(r & 15) << 4;
        #pragma unroll
        for (int j = 0; j < 4; j++) {
            float4 v0 = xr[j * 2], v1 = xr[j * 2 + 1];
            uint32_t h0, l0, h1, l1, h2, l2, h3, l3;
            cvt_pair(v0.x, v0.y, h0, l0); cvt_pair(v0.z, v0.w, h1, l1);
            cvt_pair(v1.x, v1.y, h2, l2); cvt_pair(v1.z, v1.w, h3, l3);
            uint32_t off = ((uint32_t)(q * 64 + j * 16)) ^ xop;
            *reinterpret_cast<uint4*>(bH + off) = make_uint4(h0, h1, h2, h3);
            *reinterpret_cast<uint4*>(bL + off) = make_uint4(l0, l1, l2, l3);
        }
    }
    {
        int c = tid >> 2, q = tid & 3;
        const float* wr = W + c * 131 + q * 32;
        char* bH = smem + OFF_BH + c * 256;
        char* bL = smem + OFF_BL + c * 256;
        uint32_t xop = (uint32_t)(c & 15) << 4;
        #pragma unroll
        for (int j = 0; j < 4; j++) {
            float f0 = wr[j * 8 + 0], f1 = wr[j * 8 + 1], f2 = wr[j * 8 + 2], f3 = wr[j * 8 + 3];
            float f4 = wr[j * 8 + 4], f5 = wr[j * 8 + 5], f6 = wr[j * 8 + 6], f7 = wr[j * 8 + 7];
            uint32_t h0, l0, h1, l1, h2, l2, h3, l3;
            cvt_pair(f0, f1, h0, l0); cvt_pair(f2, f3, h1, l1);
            cvt_pair(f4, f5, h2, l2); cvt_pair(f6, f7, h3, l3);
            uint32_t off = ((uint32_t)(q * 64 + j * 16)) ^ xop;
            *reinterpret_cast<uint4*>(bH + off) = make_uint4(h0, h1, h2, h3);
            *reinterpret_cast<uint4*>(bL + off) = make_uint4(l0, l1, l2, l3);
        }
    }
    if (tid < 128) {
        int c = tid;
        float4 q = make_float4(W[c * 131 + 128], W[c * 131 + 129], W[c * 131 + 130], bias[c]);
        *reinterpret_cast<float4*>(smem + OFF_Q + c * 16) = q;
    } else if (tid < 256) {
        int c = tid - 128;
        float4 e = (mat < 2)
            ? make_float4(We[c * 3], We[c * 3 + 1], We[c * 3 + 2], 0.f)
            : make_float4(0.f, 0.f, 0.f, 0.f);
        *reinterpret_cast<float4*>(smem + OFF_E + c * 16) = e;
    }
    __syncthreads();

    float acc[8][4];
    #pragma unroll
    for (int n = 0; n < 8; n++) {
        acc[n][0] = 0.f; acc[n][1] = 0.f; acc[n][2] = 0.f; acc[n][3] = 0.f;
    }
    int rg = w & 7, ch = w >> 3;
    int rA  = rg * 16 + (t & 7) + ((t >> 3) & 1) * 8;
    int hA  = t >> 4;
    uint32_t aAH = sb + OFF_AH + rA * 256;
    uint32_t aAL = sb + OFF_AL + rA * 256;
    uint32_t xopA = (uint32_t)(rA & 15) << 4;
    int rBoff = (t & 7) + ((t >> 4) << 3);
    int hB = (t >> 3) & 1;
    uint32_t xopB = (uint32_t)(rBoff & 15) << 4;

    #pragma unroll
    for (int k = 0; k < 8; k++) {
        uint32_t koffA = ((uint32_t)(k * 32 + hA * 16)) ^ xopA;
        uint32_t koffB = ((uint32_t)(k * 32 + hB * 16)) ^ xopB;
        uint32_t ah0, ah1, ah2, ah3, al0, al1, al2, al3;
        LDSM_X4(ah0, ah1, ah2, ah3, aAH + koffA);
        LDSM_X4(al0, al1, al2, al3, aAL + koffA);
        #pragma unroll
        for (int nt2 = 0; nt2 < 4; nt2++) {
            uint32_t bbase = (uint32_t)(ch * 64 + nt2 * 16 + rBoff) * 256 + koffB;
            uint32_t bh0, bh1, bh2, bh3, bl0, bl1, bl2, bl3;
            LDSM_X4(bh0, bh1, bh2, bh3, sb + OFF_BH + bbase);
            LDSM_X4(bl0, bl1, bl2, bl3, sb + OFF_BL + bbase);
            MMA16816(acc[nt2 * 2],     ah0, ah1, ah2, ah3, bh0, bh1);
            MMA16816(acc[nt2 * 2],     ah0, ah1, ah2, ah3, bl0, bl1);
            MMA16816(acc[nt2 * 2],     al0, al1, al2, al3, bh0, bh1);
            MMA16816(acc[nt2 * 2 + 1], ah0, ah1, ah2, ah3, bh2, bh3);
            MMA16816(acc[nt2 * 2 + 1], ah0, ah1, ah2, ah3, bl2, bl3);
            MMA16816(acc[nt2 * 2 + 1], al0, al1, al2, al3, bh2, bh3);
        }
    }

    {
        int mat_ = mat;
        int r0 = rg * 16 + (t >> 2);
        int node0 = rowbase + r0;
        int node1 = node0 + 8;
        float px0 = pos[node0 * 3], py0 = pos[node0 * 3 + 1], pz0 = pos[node0 * 3 + 2];
        float px1 = pos[node1 * 3], py1 = pos[node1 * 3 + 1], pz1 = pos[node1 * 3 + 2];
        #pragma unroll
        for (int nt = 0; nt < 8; nt++) {
            int c = ch * 64 + nt * 8 + (t & 3) * 2;
            float4 q0 = *reinterpret_cast<const float4*>(smem + OFF_Q + c * 16);
            float4 q1 = *reinterpret_cast<const float4*>(smem + OFF_Q + (c + 1) * 16);
            float4 e0 = *reinterpret_cast<const float4*>(smem + OFF_E + c * 16);
            float4 e1 = *reinterpret_cast<const float4*>(smem + OFF_E + (c + 1) * 16);
            float v00 = acc[nt][0] + px0 * q0.x + py0 * q0.y + pz0 * q0.z + q0.w;
            float v01 = acc[nt][1] + px0 * q1.x + py0 * q1.y + pz0 * q1.z + q1.w;
            float v10 = acc[nt][2] + px1 * q0.x + py1 * q0.y + pz1 * q0.z + q0.w;
            float v11 = acc[nt][3] + px1 * q1.x + py1 * q1.y + pz1 * q1.z + q1.w;
            float p00 = px0 * e0.x + py0 * e0.y + pz0 * e0.z;
            float p01 = px0 * e1.x + py0 * e1.y + pz0 * e1.z;
            float p10 = px1 * e0.x + py1 * e0.y + pz1 * e0.z;
            float p11 = px1 * e1.x + py1 * e1.y + pz1 * e1.z;
            size_t go0 = (size_t)node0 * HIDV + c;
            size_t go1 = (size_t)node1 * HIDV + c;
            if (mat_ == 0) {
                *reinterpret_cast<float2*>(u + go0) = make_float2(v00 - p00, v01 - p01);
                *reinterpret_cast<float2*>(u + go1) = make_float2(v10 - p10, v11 - p11);
            } else if (mat_ == 1) {
                *reinterpret_cast<float2*>(v + go0) = make_float2(v00 + p00, v01 + p01);
                *reinterpret_cast<float2*>(v + go1) = make_float2(v10 + p10, v11 + p11);
            } else {
                *reinterpret_cast<float2*>(l + go0) = make_float2(v00, v01);
                *reinterpret_cast<float2*>(l + go1) = make_float2(v10, v11);
            }
        }
    }
}

// ---------------------------------------------------------------------------
// x0 = latent @ lin0_W^T + lin0_b     (one warp per node)  [R12 verbatim]
// ---------------------------------------------------------------------------
__global__ void lin0_kernel(const float* __restrict__ latent,
                            const float* __restrict__ W,
                            const float* __restrict__ b,
                            float* __restrict__ xout, int N)
{
    int warp = (blockIdx.x * blockDim.x + threadIdx.x) >> 5;
    int lane = threadIdx.x & 31;
    if (warp >= N) return;
    const float* lrow = latent + warp * LATV;
    float l0 = lrow[lane], l1 = lrow[lane + 32];
    int f = lane * 4;
    float acc[4] = {0.f, 0.f, 0.f, 0.f};
    const float4* W4 = (const float4*)W;
    #pragma unroll
    for (int k4 = 0; k4 < 16; k4++) {
        float wv[4][4];
        #pragma unroll
        for (int q = 0; q < 4; q++) {
            float4 tt = W4[(f + q) * 16 + k4];
            wv[q][0] = tt.x; wv[q][1] = tt.y; wv[q][2] = tt.z; wv[q][3] = tt.w;
        }
        #pragma unroll
        for (int e = 0; e < 4; e++) {
            int k = k4 * 4 + e;
            float lv = __shfl_sync(0xffffffffu, (k < 32) ? l0 : l1, k & 31);
            #pragma unroll
            for (int q = 0; q < 4; q++) acc[q] += lv * wv[q][e];
        }
    }
    float4 o;
    o.x = acc[0] + b[f + 0];
    o.y = acc[1] + b[f + 1];
    o.z = acc[2] + b[f + 2];
    o.w = acc[3] + b[f + 3];
    *(float4*)(xout + warp * HIDV + f) = o;
}

// ---------------------------------------------------------------------------
// Fused GATv2 stencil, xl-free, with optional fused output head.
// [R12 verbatim except ELU uses __expf]
// ---------------------------------------------------------------------------
__global__ void gat_edge_kernel(
    const float* __restrict__ u, const float* __restrict__ v,
    const float* __restrict__ l,
    const float* __restrict__ pos,
    const float* __restrict__ att, const float* __restrict__ bias,
    const float* __restrict__ We,
    float* __restrict__ xout,
    const float* __restrict__ oW, const float* __restrict__ ob,
    float* __restrict__ fout, int N)
{
    int warp = (blockIdx.x * blockDim.x + threadIdx.x) >> 5;
    int lane = threadIdx.x & 31;
    if (warp >= N) return;
    int d = warp;
    const float4* U4 = (const float4*)u;
    const float4* V4 = (const float4*)v;
    const float4* L4 = (const float4*)l;

    float4 vd = V4[d * 32 + lane];
    float4 a4 = ((const float4*)att)[lane];

    float psx = 0.f, psy = 0.f, psz = 0.f;
    if (lane < NOFF) {
        int s = d - c_aug[lane]; if (s < 0) s += N;
        psx = pos[s * 3]; psy = pos[s * 3 + 1]; psz = pos[s * 3 + 2];
    }
    float msx = warp_sum(psx), msy = warp_sum(psy), msz = warp_sum(psz);
    float pdx = pos[d * 3], pdy = pos[d * 3 + 1], pdz = pos[d * 3 + 2];
    const float inv21 = 1.0f / 21.0f;
    float rx = pdx - msx * inv21;
    float ry = pdy - msy * inv21;
    float rz = pdz - msz * inv21;

    float wep[4][3];
    {
        int f = lane * 4;
        #pragma unroll
        for (int e = 0; e < 4; e++) {
            wep[e][0] = We[(f + e) * 3];
            wep[e][1] = We[(f + e) * 3 + 1];
            wep[e][2] = We[(f + e) * 3 + 2];
        }
    }
    float4 sc;
    sc.x = wep[0][0] * rx + wep[0][1] * ry + wep[0][2] * rz;
    sc.y = wep[1][0] * rx + wep[1][1] * ry + wep[1][2] * rz;
    sc.z = wep[2][0] * rx + wep[2][1] * ry + wep[2][2] * rz;
    sc.w = wep[3][0] * rx + wep[3][1] * ry + wep[3][2] * rz;

    if (lane == NOFF) { psx = pdx; psy = pdy; psz = pdz; }

    float4 ud = U4[d * 32 + lane];
    float a_mine = -1e30f;
    #pragma unroll
    for (int i = 0; i <= NOFF; i++) {
        float4 m;
        if (i < NOFF) {
            int s = d - c_aug[i]; if (s < 0) s += N;
            float4 us = U4[s * 32 + lane];
            m.x = us.x + vd.x; m.y = us.y + vd.y; m.z = us.z + vd.z; m.w = us.w + vd.w;
        } else {
            m.x = ud.x + vd.x + sc.x; m.y = ud.y + vd.y + sc.y;
            m.z = ud.z + vd.z + sc.z; m.w = ud.w + vd.w + sc.w;
        }
        float p = (m.x > 0.f ? m.x : 0.2f * m.x) * a4.x
                + (m.y > 0.f ? m.y : 0.2f * m.y) * a4.y
                + (m.z > 0.f ? m.z : 0.2f * m.z) * a4.z
                + (m.w > 0.f ? m.w : 0.2f * m.w) * a4.w;
        p = warp_sum(p);
        if (lane == i) a_mine = p;
    }

    float mx = warp_max(a_mine);
    float ex = (lane <= NOFF) ? __expf(a_mine - mx) : 0.f;
    float den = warp_sum(ex);
    float alpha = ex / (den + 1e-16f);

    float qx = warp_sum(alpha * psx);
    float qy = warp_sum(alpha * psy);
    float qz = warp_sum(alpha * psz);

    float4 acc = ((const float4*)bias)[lane];
    acc.x += wep[0][0] * qx + wep[0][1] * qy + wep[0][2] * qz;
    acc.y += wep[1][0] * qx + wep[1][1] * qy + wep[1][2] * qz;
    acc.z += wep[2][0] * qx + wep[2][1] * qy + wep[2][2] * qz;
    acc.w += wep[3][0] * qx + wep[3][1] * qy + wep[3][2] * qz;

    #pragma unroll
    for (int i = 0; i <= NOFF; i++) {
        float al = __shfl_sync(0xffffffffu, alpha, i);
        float4 us;
        if (i < NOFF) {
            int s = d - c_aug[i]; if (s < 0) s += N;
            us = U4[s * 32 + lane];
        } else {
            us = ud;
        }
        acc.x += al * us.x; acc.y += al * us.y;
        acc.z += al * us.z; acc.w += al * us.w;
    }

    float4 lres = L4[d * 32 + lane];
    float4 o;
    o.x = (acc.x > 0.f ? acc.x : __expf(acc.x) - 1.f) + lres.x;
    o.y = (acc.y > 0.f ? acc.y : __expf(acc.y) - 1.f) + lres.y;
    o.z = (acc.z > 0.f ? acc.z : __expf(acc.z) - 1.f) + lres.z;
    o.w = (acc.w > 0.f ? acc.w : __expf(acc.w) - 1.f) + lres.w;

    if (fout == nullptr) {
        ((float4*)xout)[d * 32 + lane] = o;
    } else {
        int f = lane * 4;
        float p0 = o.x * oW[f] + o.y * oW[f + 1] + o.z * oW[f + 2] + o.w * oW[f + 3];
        float p1 = o.x * oW[131 + f] + o.y * oW[131 + f + 1] + o.z * oW[131 + f + 2] + o.w * oW[131 + f + 3];
        float p2 = o.x * oW[262 + f] + o.y * oW[262 + f + 1] + o.z * oW[262 + f + 2] + o.w * oW[262 + f + 3];
        p0 = warp_sum(p0); p1 = warp_sum(p1); p2 = warp_sum(p2);
        if (lane == 0) {
            p0 += pdx * oW[128]       + pdy * oW[129]       + pdz * oW[130]       + ob[0];
            p1 += pdx * oW[131 + 128] + pdy * oW[131 + 129] + pdz * oW[131 + 130] + ob[1];
            p2 += pdx * oW[262 + 128] + pdy * oW[262 + 129] + pdz * oW[262 + 130] + ob[2];
            fout[d * 3] = p0; fout[d * 3 + 1] = p1; fout[d * 3 + 2] = p2;
        }
    }
}

// ---------------------------------------------------------------------------
// kNN (k=3): 4 threads per query, each scans 1024 candidates.  [R12 verbatim]
// ---------------------------------------------------------------------------
__global__ void knn_find_kernel(const float* __restrict__ pos0,
                                const float* __restrict__ pos1,
                                int* __restrict__ idx, float* __restrict__ w)
{
    __shared__ float sp[N0V * 3];
    for (int i = threadIdx.x; i < N0V * 3; i += blockDim.x) sp[i] = pos0[i];
    __syncthreads();
    int tid = threadIdx.x;
    int y = blockIdx.x * 64 + (tid >> 2);
    int seg = tid & 3;
    float px = pos1[y * 3], py = pos1[y * 3 + 1], pz = pos1[y * 3 + 2];
    float d0 = 1e30f, d1 = 1e30f, d2 = 1e30f;
    int i0 = 0, i1 = 0, i2 = 0;
    int jbeg = seg * (N0V / 4), jend = jbeg + (N0V / 4);
    for (int j = jbeg; j < jend; j++) {
        float dx = px - sp[j * 3], dy = py - sp[j * 3 + 1], dz = pz - sp[j * 3 + 2];
        float dd = dx * dx + dy * dy + dz * dz;
        if (dd < d2) {
            if (dd < d1) {
                d2 = d1; i2 = i1;
                if (dd < d0) { d1 = d0; i1 = i0; d0 = dd; i0 = j; }
                else         { d1 = dd; i1 = j; }
            } else { d2 = dd; i2 = j; }
        }
    }
    #pragma unroll
    for (int off = 1; off <= 2; off <<= 1) {
        float e0 = __shfl_xor_sync(0xffffffffu, d0, off);
        float e1 = __shfl_xor_sync(0xffffffffu, d1, off);
        float e2 = __shfl_xor_sync(0xffffffffu, d2, off);
        int   j0 = __shfl_xor_sync(0xffffffffu, i0, off);
        int   j1 = __shfl_xor_sync(0xffffffffu, i1, off);
        int   j2 = __shfl_xor_sync(0xffffffffu, i2, off);
        float a[3] = {d0, d1, d2}; int ai[3] = {i0, i1, i2};
        float b[3] = {e0, e1, e2}; int bi[3] = {j0, j1, j2};
        bool mine_first = (seg & off) == 0;
        float m[3]; int mi[3];
        int pa = 0, pb = 0;
        #pragma unroll
        for (int q = 0; q < 3; q++) {
            bool ta = mine_first ? (a[pa] <= b[pb]) : (a[pa] < b[pb]);
            m[q]  = ta ? a[pa]  : b[pb];
            mi[q] = ta ? ai[pa] : bi[pb];
            pa += ta ? 1 : 0; pb += ta ? 0 : 1;
        }
        d0 = m[0]; d1 = m[1]; d2 = m[2];
        i0 = mi[0]; i1 = mi[1]; i2 = mi[2];
    }
    if (seg == 0) {
        idx[y * 3] = i0; idx[y * 3 + 1] = i1; idx[y * 3 + 2] = i2;
        w[y * 3]     = 1.f / fmaxf(d0, 1e-16f);
        w[y * 3 + 1] = 1.f / fmaxf(d1, 1e-16f);
        w[y * 3 + 2] = 1.f / fmaxf(d2, 1e-16f);
    }
}

__global__ void knn_apply_kernel(const float* __restrict__ xin,
                                 const int* __restrict__ idx,
                                 const float* __restrict__ w,
                                 float* __restrict__ xout)
{
    int y = (blockIdx.x * blockDim.x + threadIdx.x) >> 5;
    int lane = threadIdx.x & 31;
    int i0 = idx[y * 3], i1 = idx[y * 3 + 1], i2 = idx[y * 3 + 2];
    float w0 = w[y * 3], w1 = w[y * 3 + 1], w2 = w[y * 3 + 2];
    float inv = 1.f / (w0 + w1 + w2);
    const float4* X4 = (const float4*)xin;
    float4 x0 = X4[i0 * 32 + lane], x1 = X4[i1 * 32 + lane], x2 = X4[i2 * 32 + lane];
    float4 o;
    o.x = (w0 * x0.x + w1 * x1.x + w2 * x2.x) * inv;
    o.y = (w0 * x0.y + w1 * x1.y + w2 * x2.y) * inv;
    o.z = (w0 * x0.z + w1 * x1.z + w2 * x2.z) * inv;
    o.w = (w0 * x0.w + w1 * x1.w + w2 * x2.w) * inv;
    ((float4*)xout)[y * 32 + lane] = o;
}

// ---------------------------------------------------------------------------
extern "C" void kernel_launch(void* const* d_in, const int* in_sizes, int n_in,
                              void* d_out, int out_size)
{
    const float* latent    = (const float*)d_in[0];
    const float* pos0      = (const float*)d_in[1];
    const float* pos1      = (const float*)d_in[2];
    const float* conv_Wl   = (const float*)d_in[5];
    const float* conv_bl   = (const float*)d_in[6];
    const float* conv_Wr   = (const float*)d_in[7];
    const float* conv_br   = (const float*)d_in[8];
    const float* conv_We   = (const float*)d_in[9];
    const float* conv_att  = (const float*)d_in[10];
    const float* conv_bias = (const float*)d_in[11];
    const float* lin0_W    = (const float*)d_in[12];
    const float* lin0_b    = (const float*)d_in[13];
    const float* lins_W    = (const float*)d_in[14];
    const float* lins_b    = (const float*)d_in[15];
    const float* out_W     = (const float*)d_in[16];
    const float* out_b     = (const float*)d_in[17];

    float *xa, *xb, *u, *v, *l, *w;
    int* idx;
    cudaGetSymbolAddress((void**)&xa,  g_xa);
    cudaGetSymbolAddress((void**)&xb,  g_xb);
    cudaGetSymbolAddress((void**)&u,   g_u);
    cudaGetSymbolAddress((void**)&v,   g_v);
    cudaGetSymbolAddress((void**)&l,   g_l);
    cudaGetSymbolAddress((void**)&idx, g_idx);
    cudaGetSymbolAddress((void**)&w,   g_w);

    cudaFuncSetAttribute(gemm_mma_kernel,
                         cudaFuncAttributeMaxDynamicSharedMemorySize, GSMEM_TOTAL);

    lin0_kernel<<<N0V / 8, 256>>>(latent, lin0_W, lin0_b, xa, N0V);

    for (int c = 0; c < 2; c++) {
        gemm_mma_kernel<<<dim3(N0V / 128, 3), 512, GSMEM_TOTAL>>>(
            xa, pos0,
            conv_Wl + c * HIDV * 131, conv_bl + c * HIDV,
            conv_Wr + c * HIDV * 131, conv_br + c * HIDV,
            conv_We + c * HIDV * 3,
            lins_W + c * HIDV * 131, lins_b + c * HIDV,
            u, v, l);
        gat_edge_kernel<<<N0V / 8, 256>>>(
            u, v, l, pos0,
            conv_att + c * HIDV, conv_bias + c * HIDV, conv_We + c * HIDV * 3,
            xa, nullptr, nullptr, nullptr, N0V);
    }

    knn_find_kernel<<<N1V / 64, 256>>>(pos0, pos1, idx, w);
    knn_apply_kernel<<<N1V / 8, 256>>>(xa, idx, w, xb);

    for (int c = 2; c < 4; c++) {
        gemm_mma_kernel<<<dim3(N1V / 128, 3), 512, GSMEM_TOTAL>>>(
            xb, pos1,
            conv_Wl + c * HIDV * 131, conv_bl + c * HIDV,
            conv_Wr + c * HIDV * 131, conv_br + c * HIDV,
            conv_We + c * HIDV * 3,
            lins_W + c * HIDV * 131, lins_b + c * HIDV,
            u, v, l);
        if (c == 3) {
            gat_edge_kernel<<<N1V / 8, 256>>>(
                u, v, l, pos1,
                conv_att + c * HIDV, conv_bias + c * HIDV, conv_We + c * HIDV * 3,
                nullptr, out_W, out_b, (float*)d_out, N1V);
        } else {
            gat_edge_kernel<<<N1V / 8, 256>>>(
                u, v, l, pos1,
                conv_att + c * HIDV, conv_bias + c * HIDV, conv_We + c * HIDV * 3,
                xb, nullptr, nullptr, nullptr, N1V);
        }
    }
}

// round 16
// speedup vs baseline: 1.2591x; 1.0011x over previous
#include <cuda_runtime.h>
#include <cuda_bf16.h>
#include <math.h>
#include <stdint.h>

#define N0V 4096
#define N1V 16384
#define HIDV 128
#define LATV 64
#define NOFF 21

__constant__ int c_aug[NOFF] = {1,2,3,4,5,6,7,8,9,10,11,12,13,14,15,16,17,18,19,21,24};

// scratch (static device globals; allocation-free)
__device__ float g_xa[N1V * HIDV];
__device__ float g_xb[N1V * HIDV];
__device__ float g_u [N1V * HIDV];
__device__ float g_v [N1V * HIDV];
__device__ float g_l [N1V * HIDV];
__device__ int   g_idx[N1V * 3];
__device__ float g_w  [N1V * 3];

__device__ __forceinline__ float warp_sum(float x) {
    #pragma unroll
    for (int o = 16; o; o >>= 1) x += __shfl_xor_sync(0xffffffffu, x, o);
    return x;
}
__device__ __forceinline__ float warp_max(float x) {
    #pragma unroll
    for (int o = 16; o; o >>= 1) x = fmaxf(x, __shfl_xor_sync(0xffffffffu, x, o));
    return x;
}

__device__ __forceinline__ uint32_t smem_u32(const void* p) {
    uint32_t a;
    asm("{ .reg .u64 t; cvta.to.shared.u64 t, %1; cvt.u32.u64 %0, t; }"
        : "=r"(a) : "l"(p));
    return a;
}

#define LDSM_X4(r0, r1, r2, r3, addr) \
    asm volatile("ldmatrix.sync.aligned.m8n8.x4.shared.b16 {%0,%1,%2,%3}, [%4];" \
                 : "=r"(r0), "=r"(r1), "=r"(r2), "=r"(r3) : "r"(addr))

#define MMA16816(d, a0, a1, a2, a3, b0, b1) \
    asm volatile("mma.sync.aligned.m16n8k16.row.col.f32.bf16.bf16.f32 " \
                 "{%0,%1,%2,%3}, {%4,%5,%6,%7}, {%8,%9}, {%0,%1,%2,%3};" \
                 : "+f"((d)[0]), "+f"((d)[1]), "+f"((d)[2]), "+f"((d)[3]) \
                 : "r"(a0), "r"(a1), "r"(a2), "r"(a3), "r"(b0), "r"(b1))

__device__ __forceinline__ void cvt_pair(float a, float b, uint32_t& hi, uint32_t& lo) {
    __nv_bfloat16 ha = __float2bfloat16(a), hb = __float2bfloat16(b);
    float ra = a - __bfloat162float(ha);
    float rb = b - __bfloat162float(hb);
    __nv_bfloat162 h2 = __halves2bfloat162(ha, hb);
    __nv_bfloat162 l2 = __halves2bfloat162(__float2bfloat16(ra), __float2bfloat16(rb));
    hi = *reinterpret_cast<uint32_t*>(&h2);
    lo = *reinterpret_cast<uint32_t*>(&l2);
}

// ===========================================================================
// HMMA layer GEMM (R12 verbatim: 512 threads, 128x128 tile, grid (N/128, 3);
// mat-0 epilogue writes only u = xl - pos@We^T).
// ===========================================================================
#define OFF_AH 0
#define OFF_AL 32768
#define OFF_BH 65536
#define OFF_BL 98304
#define OFF_Q  131072
#define OFF_E  133120
#define GSMEM_TOTAL 135168

__global__ void __launch_bounds__(512, 1) gemm_mma_kernel(
    const float* __restrict__ x, const float* __restrict__ pos,
    const float* __restrict__ Wl, const float* __restrict__ bl,
    const float* __restrict__ Wr, const float* __restrict__ br,
    const float* __restrict__ We,
    const float* __restrict__ Lw, const float* __restrict__ lb,
    float* __restrict__ u, float* __restrict__ v, float* __restrict__ l)
{
    extern __shared__ char smem[];
    uint32_t sb = smem_u32(smem);
    int tid = threadIdx.x;
    int w = tid >> 5, t = tid & 31;
    int mat = blockIdx.y;
    int rowbase = blockIdx.x * 128;
    const float* W    = (mat == 0) ? Wl : (mat == 1) ? Wr : Lw;
    const float* bias = (mat == 0) ? bl : (mat == 1) ? br : lb;

    {
        int r = tid >> 2, q = tid & 3;
        const float4* xr = (const float4*)(x + (size_t)(rowbase + r) * HIDV + q * 32);
        char* bH = smem + OFF_AH + r * 256;
        char* bL = smem + OFF_AL + r * 256;
        uint32_t xop = (uint32_t)(r & 15) << 4;
        #pragma unroll
        for (int j = 0; j < 4; j++) {
            float4 v0 = xr[j * 2], v1 = xr[j * 2 + 1];
            uint32_t h0, l0, h1, l1, h2, l2, h3, l3;
            cvt_pair(v0.x, v0.y, h0, l0); cvt_pair(v0.z, v0.w, h1, l1);
            cvt_pair(v1.x, v1.y, h2, l2); cvt_pair(v1.z, v1.w, h3, l3);
            uint32_t off = ((uint32_t)(q * 64 + j * 16)) ^ xop;
            *reinterpret_cast<uint4*>(bH + off) = make_uint4(h0, h1, h2, h3);
            *reinterpret_cast<uint4*>(bL + off) = make_uint4(l0, l1, l2, l3);
        }
    }
    {
        int c = tid >> 2, q = tid & 3;
        const float* wr = W + c * 131 + q * 32;
        char* bH = smem + OFF_BH + c * 256;
        char* bL = smem + OFF_BL + c * 256;
        uint32_t xop = (uint32_t)(c & 15) << 4;
        #pragma unroll
        for (int j = 0; j < 4; j++) {
            float f0 = wr[j * 8 + 0], f1 = wr[j * 8 + 1], f2 = wr[j * 8 + 2], f3 = wr[j * 8 + 3];
            float f4 = wr[j * 8 + 4], f5 = wr[j * 8 + 5], f6 = wr[j * 8 + 6], f7 = wr[j * 8 + 7];
            uint32_t h0, l0, h1, l1, h2, l2, h3, l3;
            cvt_pair(f0, f1, h0, l0); cvt_pair(f2, f3, h1, l1);
            cvt_pair(f4, f5, h2, l2); cvt_pair(f6, f7, h3, l3);
            uint32_t off = ((uint32_t)(q * 64 + j * 16)) ^ xop;
            *reinterpret_cast<uint4*>(bH + off) = make_uint4(h0, h1, h2, h3);
            *reinterpret_cast<uint4*>(bL + off) = make_uint4(l0, l1, l2, l3);
        }
    }
    if (tid < 128) {
        int c = tid;
        float4 q = make_float4(W[c * 131 + 128], W[c * 131 + 129], W[c * 131 + 130], bias[c]);
        *reinterpret_cast<float4*>(smem + OFF_Q + c * 16) = q;
    } else if (tid < 256) {
        int c = tid - 128;
        float4 e = (mat < 2)
            ? make_float4(We[c * 3], We[c * 3 + 1], We[c * 3 + 2], 0.f)
            : make_float4(0.f, 0.f, 0.f, 0.f);
        *reinterpret_cast<float4*>(smem + OFF_E + c * 16) = e;
    }
    __syncthreads();

    float acc[8][4];
    #pragma unroll
    for (int n = 0; n < 8; n++) {
        acc[n][0] = 0.f; acc[n][1] = 0.f; acc[n][2] = 0.f; acc[n][3] = 0.f;
    }
    int rg = w & 7, ch = w >> 3;
    int rA  = rg * 16 + (t & 7) + ((t >> 3) & 1) * 8;
    int hA  = t >> 4;
    uint32_t aAH = sb + OFF_AH + rA * 256;
    uint32_t aAL = sb + OFF_AL + rA * 256;
    uint32_t xopA = (uint32_t)(rA & 15) << 4;
    int rBoff = (t & 7) + ((t >> 4) << 3);
    int hB = (t >> 3) & 1;
    uint32_t xopB = (uint32_t)(rBoff & 15) << 4;

    #pragma unroll
    for (int k = 0; k < 8; k++) {
        uint32_t koffA = ((uint32_t)(k * 32 + hA * 16)) ^ xopA;
        uint32_t koffB = ((uint32_t)(k * 32 + hB * 16)) ^ xopB;
        uint32_t ah0, ah1, ah2, ah3, al0, al1, al2, al3;
        LDSM_X4(ah0, ah1, ah2, ah3, aAH + koffA);
        LDSM_X4(al0, al1, al2, al3, aAL + koffA);
        #pragma unroll
        for (int nt2 = 0; nt2 < 4; nt2++) {
            uint32_t bbase = (uint32_t)(ch * 64 + nt2 * 16 + rBoff) * 256 + koffB;
            uint32_t bh0, bh1, bh2, bh3, bl0, bl1, bl2, bl3;
            LDSM_X4(bh0, bh1, bh2, bh3, sb + OFF_BH + bbase);
            LDSM_X4(bl0, bl1, bl2, bl3, sb + OFF_BL + bbase);
            MMA16816(acc[nt2 * 2],     ah0, ah1, ah2, ah3, bh0, bh1);
            MMA16816(acc[nt2 * 2],     ah0, ah1, ah2, ah3, bl0, bl1);
            MMA16816(acc[nt2 * 2],     al0, al1, al2, al3, bh0, bh1);
            MMA16816(acc[nt2 * 2 + 1], ah0, ah1, ah2, ah3, bh2, bh3);
            MMA16816(acc[nt2 * 2 + 1], ah0, ah1, ah2, ah3, bl2, bl3);
            MMA16816(acc[nt2 * 2 + 1], al0, al1, al2, al3, bh2, bh3);
        }
    }

    {
        int mat_ = mat;
        int r0 = rg * 16 + (t >> 2);
        int node0 = rowbase + r0;
        int node1 = node0 + 8;
        float px0 = pos[node0 * 3], py0 = pos[node0 * 3 + 1], pz0 = pos[node0 * 3 + 2];
        float px1 = pos[node1 * 3], py1 = pos[node1 * 3 + 1], pz1 = pos[node1 * 3 + 2];
        #pragma unroll
        for (int nt = 0; nt < 8; nt++) {
            int c = ch * 64 + nt * 8 + (t & 3) * 2;
            float4 q0 = *reinterpret_cast<const float4*>(smem + OFF_Q + c * 16);
            float4 q1 = *reinterpret_cast<const float4*>(smem + OFF_Q + (c + 1) * 16);
            float4 e0 = *reinterpret_cast<const float4*>(smem + OFF_E + c * 16);
            float4 e1 = *reinterpret_cast<const float4*>(smem + OFF_E + (c + 1) * 16);
            float v00 = acc[nt][0] + px0 * q0.x + py0 * q0.y + pz0 * q0.z + q0.w;
            float v01 = acc[nt][1] + px0 * q1.x + py0 * q1.y + pz0 * q1.z + q1.w;
            float v10 = acc[nt][2] + px1 * q0.x + py1 * q0.y + pz1 * q0.z + q0.w;
            float v11 = acc[nt][3] + px1 * q1.x + py1 * q1.y + pz1 * q1.z + q1.w;
            float p00 = px0 * e0.x + py0 * e0.y + pz0 * e0.z;
            float p01 = px0 * e1.x + py0 * e1.y + pz0 * e1.z;
            float p10 = px1 * e0.x + py1 * e0.y + pz1 * e0.z;
            float p11 = px1 * e1.x + py1 * e1.y + pz1 * e1.z;
            size_t go0 = (size_t)node0 * HIDV + c;
            size_t go1 = (size_t)node1 * HIDV + c;
            if (mat_ == 0) {
                *reinterpret_cast<float2*>(u + go0) = make_float2(v00 - p00, v01 - p01);
                *reinterpret_cast<float2*>(u + go1) = make_float2(v10 - p10, v11 - p11);
            } else if (mat_ == 1) {
                *reinterpret_cast<float2*>(v + go0) = make_float2(v00 + p00, v01 + p01);
                *reinterpret_cast<float2*>(v + go1) = make_float2(v10 + p10, v11 + p11);
            } else {
                *reinterpret_cast<float2*>(l + go0) = make_float2(v00, v01);
                *reinterpret_cast<float2*>(l + go1) = make_float2(v10, v11);
            }
        }
    }
}

// ---------------------------------------------------------------------------
// x0 = latent @ lin0_W^T + lin0_b     (one warp per node)  [R15 verbatim]
// ---------------------------------------------------------------------------
__global__ void lin0_kernel(const float* __restrict__ latent,
                            const float* __restrict__ W,
                            const float* __restrict__ b,
                            float* __restrict__ xout, int N)
{
    int warp = (blockIdx.x * blockDim.x + threadIdx.x) >> 5;
    int lane = threadIdx.x & 31;
    if (warp >= N) return;
    const float* lrow = latent + warp * LATV;
    float l0 = lrow[lane], l1 = lrow[lane + 32];
    int f = lane * 4;
    float acc[4] = {0.f, 0.f, 0.f, 0.f};
    const float4* W4 = (const float4*)W;
    #pragma unroll
    for (int k4 = 0; k4 < 16; k4++) {
        float wv[4][4];
        #pragma unroll
        for (int q = 0; q < 4; q++) {
            float4 tt = W4[(f + q) * 16 + k4];
            wv[q][0] = tt.x; wv[q][1] = tt.y; wv[q][2] = tt.z; wv[q][3] = tt.w;
        }
        #pragma unroll
        for (int e = 0; e < 4; e++) {
            int k = k4 * 4 + e;
            float lv = __shfl_sync(0xffffffffu, (k < 32) ? l0 : l1, k & 31);
            #pragma unroll
            for (int q = 0; q < 4; q++) acc[q] += lv * wv[q][e];
        }
    }
    float4 o;
    o.x = acc[0] + b[f + 0];
    o.y = acc[1] + b[f + 1];
    o.z = acc[2] + b[f + 2];
    o.w = acc[3] + b[f + 3];
    *(float4*)(xout + warp * HIDV + f) = o;
}

// ---------------------------------------------------------------------------
// Fused GATv2 stencil, xl-free, optional fused output head. [R15 verbatim]
// ---------------------------------------------------------------------------
__global__ void gat_edge_kernel(
    const float* __restrict__ u, const float* __restrict__ v,
    const float* __restrict__ l,
    const float* __restrict__ pos,
    const float* __restrict__ att, const float* __restrict__ bias,
    const float* __restrict__ We,
    float* __restrict__ xout,
    const float* __restrict__ oW, const float* __restrict__ ob,
    float* __restrict__ fout, int N)
{
    int warp = (blockIdx.x * blockDim.x + threadIdx.x) >> 5;
    int lane = threadIdx.x & 31;
    if (warp >= N) return;
    int d = warp;
    const float4* U4 = (const float4*)u;
    const float4* V4 = (const float4*)v;
    const float4* L4 = (const float4*)l;

    float4 vd = V4[d * 32 + lane];
    float4 a4 = ((const float4*)att)[lane];

    float psx = 0.f, psy = 0.f, psz = 0.f;
    if (lane < NOFF) {
        int s = d - c_aug[lane]; if (s < 0) s += N;
        psx = pos[s * 3]; psy = pos[s * 3 + 1]; psz = pos[s * 3 + 2];
    }
    float msx = warp_sum(psx), msy = warp_sum(psy), msz = warp_sum(psz);
    float pdx = pos[d * 3], pdy = pos[d * 3 + 1], pdz = pos[d * 3 + 2];
    const float inv21 = 1.0f / 21.0f;
    float rx = pdx - msx * inv21;
    float ry = pdy - msy * inv21;
    float rz = pdz - msz * inv21;

    float wep[4][3];
    {
        int f = lane * 4;
        #pragma unroll
        for (int e = 0; e < 4; e++) {
            wep[e][0] = We[(f + e) * 3];
            wep[e][1] = We[(f + e) * 3 + 1];
            wep[e][2] = We[(f + e) * 3 + 2];
        }
    }
    float4 sc;
    sc.x = wep[0][0] * rx + wep[0][1] * ry + wep[0][2] * rz;
    sc.y = wep[1][0] * rx + wep[1][1] * ry + wep[1][2] * rz;
    sc.z = wep[2][0] * rx + wep[2][1] * ry + wep[2][2] * rz;
    sc.w = wep[3][0] * rx + wep[3][1] * ry + wep[3][2] * rz;

    if (lane == NOFF) { psx = pdx; psy = pdy; psz = pdz; }

    float4 ud = U4[d * 32 + lane];
    float a_mine = -1e30f;
    #pragma unroll
    for (int i = 0; i <= NOFF; i++) {
        float4 m;
        if (i < NOFF) {
            int s = d - c_aug[i]; if (s < 0) s += N;
            float4 us = U4[s * 32 + lane];
            m.x = us.x + vd.x; m.y = us.y + vd.y; m.z = us.z + vd.z; m.w = us.w + vd.w;
        } else {
            m.x = ud.x + vd.x + sc.x; m.y = ud.y + vd.y + sc.y;
            m.z = ud.z + vd.z + sc.z; m.w = ud.w + vd.w + sc.w;
        }
        float p = (m.x > 0.f ? m.x : 0.2f * m.x) * a4.x
                + (m.y > 0.f ? m.y : 0.2f * m.y) * a4.y
                + (m.z > 0.f ? m.z : 0.2f * m.z) * a4.z
                + (m.w > 0.f ? m.w : 0.2f * m.w) * a4.w;
        p = warp_sum(p);
        if (lane == i) a_mine = p;
    }

    float mx = warp_max(a_mine);
    float ex = (lane <= NOFF) ? __expf(a_mine - mx) : 0.f;
    float den = warp_sum(ex);
    float alpha = ex / (den + 1e-16f);

    float qx = warp_sum(alpha * psx);
    float qy = warp_sum(alpha * psy);
    float qz = warp_sum(alpha * psz);

    float4 acc = ((const float4*)bias)[lane];
    acc.x += wep[0][0] * qx + wep[0][1] * qy + wep[0][2] * qz;
    acc.y += wep[1][0] * qx + wep[1][1] * qy + wep[1][2] * qz;
    acc.z += wep[2][0] * qx + wep[2][1] * qy + wep[2][2] * qz;
    acc.w += wep[3][0] * qx + wep[3][1] * qy + wep[3][2] * qz;

    #pragma unroll
    for (int i = 0; i <= NOFF; i++) {
        float al = __shfl_sync(0xffffffffu, alpha, i);
        float4 us;
        if (i < NOFF) {
            int s = d - c_aug[i]; if (s < 0) s += N;
            us = U4[s * 32 + lane];
        } else {
            us = ud;
        }
        acc.x += al * us.x; acc.y += al * us.y;
        acc.z += al * us.z; acc.w += al * us.w;
    }

    float4 lres = L4[d * 32 + lane];
    float4 o;
    o.x = (acc.x > 0.f ? acc.x : __expf(acc.x) - 1.f) + lres.x;
    o.y = (acc.y > 0.f ? acc.y : __expf(acc.y) - 1.f) + lres.y;
    o.z = (acc.z > 0.f ? acc.z : __expf(acc.z) - 1.f) + lres.z;
    o.w = (acc.w > 0.f ? acc.w : __expf(acc.w) - 1.f) + lres.w;

    if (fout == nullptr) {
        ((float4*)xout)[d * 32 + lane] = o;
    } else {
        int f = lane * 4;
        float p0 = o.x * oW[f] + o.y * oW[f + 1] + o.z * oW[f + 2] + o.w * oW[f + 3];
        float p1 = o.x * oW[131 + f] + o.y * oW[131 + f + 1] + o.z * oW[131 + f + 2] + o.w * oW[131 + f + 3];
        float p2 = o.x * oW[262 + f] + o.y * oW[262 + f + 1] + o.z * oW[262 + f + 2] + o.w * oW[262 + f + 3];
        p0 = warp_sum(p0); p1 = warp_sum(p1); p2 = warp_sum(p2);
        if (lane == 0) {
            p0 += pdx * oW[128]       + pdy * oW[129]       + pdz * oW[130]       + ob[0];
            p1 += pdx * oW[131 + 128] + pdy * oW[131 + 129] + pdz * oW[131 + 130] + ob[1];
            p2 += pdx * oW[262 + 128] + pdy * oW[262 + 129] + pdz * oW[262 + 130] + ob[2];
            fout[d * 3] = p0; fout[d * 3 + 1] = p1; fout[d * 3 + 2] = p2;
        }
    }
}

// ---------------------------------------------------------------------------
// kNN (k=3): 4 threads per query; scan loop unrolled x4 to overlap LDS latency.
// Candidates still inserted in index order -> identical tie-breaking.
// ---------------------------------------------------------------------------
__global__ void knn_find_kernel(const float* __restrict__ pos0,
                                const float* __restrict__ pos1,
                                int* __restrict__ idx, float* __restrict__ w)
{
    __shared__ float sp[N0V * 3];
    for (int i = threadIdx.x; i < N0V * 3; i += blockDim.x) sp[i] = pos0[i];
    __syncthreads();
    int tid = threadIdx.x;
    int y = blockIdx.x * 64 + (tid >> 2);
    int seg = tid & 3;
    float px = pos1[y * 3], py = pos1[y * 3 + 1], pz = pos1[y * 3 + 2];
    float d0 = 1e30f, d1 = 1e30f, d2 = 1e30f;
    int i0 = 0, i1 = 0, i2 = 0;
    int jbeg = seg * (N0V / 4);
    for (int jj = 0; jj < N0V / 4; jj += 4) {
        int j = jbeg + jj;
        // batch-load 4 candidates (independent LDS, latencies overlap)
        float dd[4];
        #pragma unroll
        for (int q = 0; q < 4; q++) {
            float dx = px - sp[(j + q) * 3];
            float dy = py - sp[(j + q) * 3 + 1];
            float dz = pz - sp[(j + q) * 3 + 2];
            dd[q] = dx * dx + dy * dy + dz * dz;
        }
        // sequential insertion preserves index-order tie-breaking
        #pragma unroll
        for (int q = 0; q < 4; q++) {
            float ddq = dd[q];
            if (ddq < d2) {
                if (ddq < d1) {
                    d2 = d1; i2 = i1;
                    if (ddq < d0) { d1 = d0; i1 = i0; d0 = ddq; i0 = j + q; }
                    else          { d1 = ddq; i1 = j + q; }
                } else { d2 = ddq; i2 = j + q; }
            }
        }
    }
    #pragma unroll
    for (int off = 1; off <= 2; off <<= 1) {
        float e0 = __shfl_xor_sync(0xffffffffu, d0, off);
        float e1 = __shfl_xor_sync(0xffffffffu, d1, off);
        float e2 = __shfl_xor_sync(0xffffffffu, d2, off);
        int   j0 = __shfl_xor_sync(0xffffffffu, i0, off);
        int   j1 = __shfl_xor_sync(0xffffffffu, i1, off);
        int   j2 = __shfl_xor_sync(0xffffffffu, i2, off);
        float a[3] = {d0, d1, d2}; int ai[3] = {i0, i1, i2};
        float b[3] = {e0, e1, e2}; int bi[3] = {j0, j1, j2};
        bool mine_first = (seg & off) == 0;
        float m[3]; int mi[3];
        int pa = 0, pb = 0;
        #pragma unroll
        for (int q = 0; q < 3; q++) {
            bool ta = mine_first ? (a[pa] <= b[pb]) : (a[pa] < b[pb]);
            m[q]  = ta ? a[pa]  : b[pb];
            mi[q] = ta ? ai[pa] : bi[pb];
            pa += ta ? 1 : 0; pb += ta ? 0 : 1;
        }
        d0 = m[0]; d1 = m[1]; d2 = m[2];
        i0 = mi[0]; i1 = mi[1]; i2 = mi[2];
    }
    if (seg == 0) {
        idx[y * 3] = i0; idx[y * 3 + 1] = i1; idx[y * 3 + 2] = i2;
        w[y * 3]     = 1.f / fmaxf(d0, 1e-16f);
        w[y * 3 + 1] = 1.f / fmaxf(d1, 1e-16f);
        w[y * 3 + 2] = 1.f / fmaxf(d2, 1e-16f);
    }
}

__global__ void knn_apply_kernel(const float* __restrict__ xin,
                                 const int* __restrict__ idx,
                                 const float* __restrict__ w,
                                 float* __restrict__ xout)
{
    int y = (blockIdx.x * blockDim.x + threadIdx.x) >> 5;
    int lane = threadIdx.x & 31;
    int i0 = idx[y * 3], i1 = idx[y * 3 + 1], i2 = idx[y * 3 + 2];
    float w0 = w[y * 3], w1 = w[y * 3 + 1], w2 = w[y * 3 + 2];
    float inv = 1.f / (w0 + w1 + w2);
    const float4* X4 = (const float4*)xin;
    float4 x0 = X4[i0 * 32 + lane], x1 = X4[i1 * 32 + lane], x2 = X4[i2 * 32 + lane];
    float4 o;
    o.x = (w0 * x0.x + w1 * x1.x + w2 * x2.x) * inv;
    o.y = (w0 * x0.y + w1 * x1.y + w2 * x2.y) * inv;
    o.z = (w0 * x0.z + w1 * x1.z + w2 * x2.z) * inv;
    o.w = (w0 * x0.w + w1 * x1.w + w2 * x2.w) * inv;
    ((float4*)xout)[y * 32 + lane] = o;
}

// ---------------------------------------------------------------------------
extern "C" void kernel_launch(void* const* d_in, const int* in_sizes, int n_in,
                              void* d_out, int out_size)
{
    const float* latent    = (const float*)d_in[0];
    const float* pos0      = (const float*)d_in[1];
    const float* pos1      = (const float*)d_in[2];
    const float* conv_Wl   = (const float*)d_in[5];
    const float* conv_bl   = (const float*)d_in[6];
    const float* conv_Wr   = (const float*)d_in[7];
    const float* conv_br   = (const float*)d_in[8];
    const float* conv_We   = (const float*)d_in[9];
    const float* conv_att  = (const float*)d_in[10];
    const float* conv_bias = (const float*)d_in[11];
    const float* lin0_W    = (const float*)d_in[12];
    const float* lin0_b    = (const float*)d_in[13];
    const float* lins_W    = (const float*)d_in[14];
    const float* lins_b    = (const float*)d_in[15];
    const float* out_W     = (const float*)d_in[16];
    const float* out_b     = (const float*)d_in[17];

    float *xa, *xb, *u, *v, *l, *w;
    int* idx;
    cudaGetSymbolAddress((void**)&xa,  g_xa);
    cudaGetSymbolAddress((void**)&xb,  g_xb);
    cudaGetSymbolAddress((void**)&u,   g_u);
    cudaGetSymbolAddress((void**)&v,   g_v);
    cudaGetSymbolAddress((void**)&l,   g_l);
    cudaGetSymbolAddress((void**)&idx, g_idx);
    cudaGetSymbolAddress((void**)&w,   g_w);

    cudaFuncSetAttribute(gemm_mma_kernel,
                         cudaFuncAttributeMaxDynamicSharedMemorySize, GSMEM_TOTAL);

    lin0_kernel<<<N0V / 8, 256>>>(latent, lin0_W, lin0_b, xa, N0V);

    for (int c = 0; c < 2; c++) {
        gemm_mma_kernel<<<dim3(N0V / 128, 3), 512, GSMEM_TOTAL>>>(
            xa, pos0,
            conv_Wl + c * HIDV * 131, conv_bl + c * HIDV,
            conv_Wr + c * HIDV * 131, conv_br + c * HIDV,
            conv_We + c * HIDV * 3,
            lins_W + c * HIDV * 131, lins_b + c * HIDV,
            u, v, l);
        gat_edge_kernel<<<N0V / 8, 256>>>(
            u, v, l, pos0,
            conv_att + c * HIDV, conv_bias + c * HIDV, conv_We + c * HIDV * 3,
            xa, nullptr, nullptr, nullptr, N0V);
    }

    knn_find_kernel<<<N1V / 64, 256>>>(pos0, pos1, idx, w);
    knn_apply_kernel<<<N1V / 8, 256>>>(xa, idx, w, xb);

    for (int c = 2; c < 4; c++) {
        gemm_mma_kernel<<<dim3(N1V / 128, 3), 512, GSMEM_TOTAL>>>(
            xb, pos1,
            conv_Wl + c * HIDV * 131, conv_bl + c * HIDV,
            conv_Wr + c * HIDV * 131, conv_br + c * HIDV,
            conv_We + c * HIDV * 3,
            lins_W + c * HIDV * 131, lins_b + c * HIDV,
            u, v, l);
        if (c == 3) {
            gat_edge_kernel<<<N1V / 8, 256>>>(
                u, v, l, pos1,
                conv_att + c * HIDV, conv_bias + c * HIDV, conv_We + c * HIDV * 3,
                nullptr, out_W, out_b, (float*)d_out, N1V);
        } else {
            gat_edge_kernel<<<N1V / 8, 256>>>(
                u, v, l, pos1,
                conv_att + c * HIDV, conv_bias + c * HIDV, conv_We + c * HIDV * 3,
                xb, nullptr, nullptr, nullptr, N1V);
        }
    }
}